// round 11
// baseline (speedup 1.0000x reference)
#include <cuda_runtime.h>
#include <cuda_bf16.h>
#include <cuda_fp16.h>
#include <cstdint>

// Problem constants
#define BB 4
#define SS 2048
#define DD 1024
#define HH 16
#define HDIM 64
#define MM (BB * SS)   // 8192

// log2(e) * 0.125 (softmax scale folded into Q, exp2 domain)
#define QSC 0.18033688011112042f

// ---------------------------------------------------------------------------
// Device-global scratch (allocation-free rule)
// ---------------------------------------------------------------------------
__device__ __nv_bfloat16 g_xhi[(size_t)MM * DD], g_xlo[(size_t)MM * DD];
__device__ __nv_bfloat16 g_Wqh[DD * DD], g_Wql[DD * DD];
__device__ __nv_bfloat16 g_Wkh[DD * DD], g_Wkl[DD * DD];
__device__ __nv_bfloat16 g_Wvh[DD * DD], g_Wvl[DD * DD];
__device__ __nv_bfloat16 g_Woh[DD * DD], g_Wol[DD * DD];
__device__ __half g_Qh[(size_t)MM * DD];    // single fp16 (scaled)
__device__ __half g_Kh[(size_t)MM * DD];    // single fp16
__device__ __half g_Vh[(size_t)MM * DD];    // single fp16
__device__ __nv_bfloat16 g_Ahi[(size_t)MM * DD], g_Alo[(size_t)MM * DD];
__device__ float g_cos[SS * 32];
__device__ float g_sin[SS * 32];

// ---------------------------------------------------------------------------
// PTX helpers (portable sm_80+: ldmatrix, mma.sync, cp.async)
// ---------------------------------------------------------------------------
__device__ __forceinline__ uint32_t smem_u32(const void* p) {
    uint32_t a;
    asm("{ .reg .u64 t; cvta.to.shared.u64 t, %1; cvt.u32.u64 %0, t; }"
        : "=r"(a) : "l"(p));
    return a;
}

__device__ __forceinline__ void ldsm4(uint32_t* r, uint32_t addr) {
    asm volatile("ldmatrix.sync.aligned.m8n8.x4.shared.b16 {%0,%1,%2,%3}, [%4];"
        : "=r"(r[0]), "=r"(r[1]), "=r"(r[2]), "=r"(r[3]) : "r"(addr));
}

__device__ __forceinline__ void ldsm4t(uint32_t* r, uint32_t addr) {
    asm volatile("ldmatrix.sync.aligned.m8n8.x4.trans.shared.b16 {%0,%1,%2,%3}, [%4];"
        : "=r"(r[0]), "=r"(r[1]), "=r"(r[2]), "=r"(r[3]) : "r"(addr));
}

__device__ __forceinline__ void mma_bf16(float* c, const uint32_t* a, const uint32_t* b) {
    asm volatile(
        "mma.sync.aligned.m16n8k16.row.col.f32.bf16.bf16.f32 "
        "{%0,%1,%2,%3}, {%4,%5,%6,%7}, {%8,%9}, {%0,%1,%2,%3};"
        : "+f"(c[0]), "+f"(c[1]), "+f"(c[2]), "+f"(c[3])
        : "r"(a[0]), "r"(a[1]), "r"(a[2]), "r"(a[3]), "r"(b[0]), "r"(b[1]));
}

__device__ __forceinline__ void mma_f16(float* c, const uint32_t* a, const uint32_t* b) {
    asm volatile(
        "mma.sync.aligned.m16n8k16.row.col.f32.f16.f16.f32 "
        "{%0,%1,%2,%3}, {%4,%5,%6,%7}, {%8,%9}, {%0,%1,%2,%3};"
        : "+f"(c[0]), "+f"(c[1]), "+f"(c[2]), "+f"(c[3])
        : "r"(a[0]), "r"(a[1]), "r"(a[2]), "r"(a[3]), "r"(b[0]), "r"(b[1]));
}

__device__ __forceinline__ void cp16(uint32_t dst, const void* src) {
    asm volatile("cp.async.cg.shared.global [%0], [%1], 16;" :: "r"(dst), "l"(src));
}
#define CP_COMMIT() asm volatile("cp.async.commit_group;" ::: "memory")
#define CP_WAIT(n)  asm volatile("cp.async.wait_group %0;" :: "n"(n) : "memory")

// fp32 pair -> packed bf16x2 hi + bf16x2 lo (residual)
__device__ __forceinline__ void cvt_split2(float v0, float v1, uint32_t& h, uint32_t& l) {
    asm("cvt.rn.bf16x2.f32 %0, %1, %2;" : "=r"(h) : "f"(v1), "f"(v0));
    float r0 = v0 - __uint_as_float(h << 16);
    float r1 = v1 - __uint_as_float(h & 0xffff0000u);
    asm("cvt.rn.bf16x2.f32 %0, %1, %2;" : "=r"(l) : "f"(r1), "f"(r0));
}

// fp32 pair -> packed f16x2 (lo half = v0)
__device__ __forceinline__ uint32_t pack_f16(float v0, float v1) {
    uint32_t r;
    asm("cvt.rn.f16x2.f32 %0, %1, %2;" : "=r"(r) : "f"(v1), "f"(v0));
    return r;
}

// ---------------------------------------------------------------------------
// Fused prep: rope tables + x split + 4 weight splits, one launch.
// blocks [0,8192) = x, [8192,12288) = weights (1024 each), [12288,12544) = rope
// ---------------------------------------------------------------------------
__global__ __launch_bounds__(256) void prep_kernel(
    const float* __restrict__ x,
    const float* __restrict__ Wq, const float* __restrict__ Wk,
    const float* __restrict__ Wv, const float* __restrict__ Wo)
{
    const int bid = blockIdx.x;
    const int tid = threadIdx.x;

    if (bid < 8192) {                       // x: 2097152 float4 chunks
        int i = bid * 256 + tid;
        float4 v = ((const float4*)x)[i];
        uint32_t h01, h23, l01, l23;
        cvt_split2(v.x, v.y, h01, l01);
        cvt_split2(v.z, v.w, h23, l23);
        ((uint2*)g_xhi)[i] = make_uint2(h01, h23);
        ((uint2*)g_xlo)[i] = make_uint2(l01, l23);
    } else if (bid < 12288) {               // weights
        int wb = bid - 8192;
        int z = wb >> 10;
        const float* src = (z == 0) ? Wq : (z == 1) ? Wk : (z == 2) ? Wv : Wo;
        __nv_bfloat16* hi = (z == 0) ? g_Wqh : (z == 1) ? g_Wkh : (z == 2) ? g_Wvh : g_Woh;
        __nv_bfloat16* lo = (z == 0) ? g_Wql : (z == 1) ? g_Wkl : (z == 2) ? g_Wvl : g_Wol;
        int i = (wb & 1023) * 256 + tid;
        float4 v = ((const float4*)src)[i];
        uint32_t h01, h23, l01, l23;
        cvt_split2(v.x, v.y, h01, l01);
        cvt_split2(v.z, v.w, h23, l23);
        ((uint2*)hi)[i] = make_uint2(h01, h23);
        ((uint2*)lo)[i] = make_uint2(l01, l23);
    } else {                                // rope tables: S*32 entries
        int idx = (bid - 12288) * 256 + tid;
        int i = idx & 31;
        int s = idx >> 5;
        double inv_freq = exp((double)i * -0.28782313662425575);  // -ln(10000)/32
        double sd, cd;
        sincos((double)s * inv_freq, &sd, &cd);
        g_cos[idx] = (float)cd;
        g_sin[idx] = (float)sd;
    }
}

// ---------------------------------------------------------------------------
// GEMM core (bf16 3-term): 128x256 CTA, 8 warps (64x64 each: 2m x 4n),
// K-chunk 32, 2-stage cp.async, 120 KB smem, 1 CTA/SM.
// MMA/LDSM ratio 6 (was 4): per kk, 16 ldsm feed 96 MMAs.
// Per-acc accumulation order unchanged (hh -> hl -> lh per kk) => bit-exact.
// Stage (61440B): Ahi[128x80] | Alo | Bhi[256x80] | Blo
// ---------------------------------------------------------------------------
#define GARR_A 10240            // 128 * 80
#define GARR_B 20480            // 256 * 80
#define GSTAGE 61440
#define GSMEM_TOTAL (2 * GSTAGE)   // 122880

__device__ __forceinline__ void gemm_core(
    const __nv_bfloat16* __restrict__ Ahi, const __nv_bfloat16* __restrict__ Alo,
    const __nv_bfloat16* __restrict__ Bhi, const __nv_bfloat16* __restrict__ Blo,
    uint32_t smb, int tid, int wid, int lid, float acc[4][8][4])
{
    const int warp_m = wid & 1, warp_n = wid >> 1;   // 2 x 4
    const int arow = lid & 15;
    const int ak16 = (lid & 16);
    const int brow = (lid & 7) | ((lid & 16) >> 1);
    const int bk16 = (lid & 8) * 2;
    const uint32_t aBase = smb + (uint32_t)(warp_m * 64 + arow) * 80 + ak16;
    const uint32_t bBase = smb + 2 * GARR_A
        + (uint32_t)(warp_n * 64 + brow) * 80 + bk16;

    auto issue = [&](int ck) {
        const uint32_t base = smb + (uint32_t)(ck & 1) * GSTAGE;
        const int k0 = ck * 32;
        // A arrays: 128 rows x 4 chunks = 512 each
#pragma unroll
        for (int a = 0; a < 2; a++) {
#pragma unroll
            for (int i = 0; i < 2; i++) {
                int idx = tid + i * 256;
                int row = idx >> 2, q = idx & 3;
                const __nv_bfloat16* s = (a == 0) ? Ahi : Alo;
                cp16(base + a * GARR_A + row * 80 + q * 16,
                     s + (size_t)row * DD + k0 + q * 8);
            }
        }
        // B arrays: 256 rows x 4 chunks = 1024 each
#pragma unroll
        for (int a = 0; a < 2; a++) {
#pragma unroll
            for (int i = 0; i < 4; i++) {
                int idx = tid + i * 256;
                int row = idx >> 2, q = idx & 3;
                const __nv_bfloat16* s = (a == 0) ? Bhi : Blo;
                cp16(base + 2 * GARR_A + a * GARR_B + row * 80 + q * 16,
                     s + (size_t)row * DD + k0 + q * 8);
            }
        }
    };

    issue(0); CP_COMMIT();
    issue(1); CP_COMMIT();

    const int nchunks = DD / 32;   // 32
    for (int ck = 0; ck < nchunks; ck++) {
        CP_WAIT(1);
        __syncthreads();

        const uint32_t bo = (uint32_t)(ck & 1) * GSTAGE;
#pragma unroll
        for (int kk = 0; kk < 2; kk++) {
            uint32_t af[4][4], bf[4][4], bf2[4][4];
            const uint32_t ka = aBase + bo + kk * 32;
            const uint32_t kb = bBase + bo + kk * 32;
            // hi operands
#pragma unroll
            for (int mt = 0; mt < 4; mt++) ldsm4(af[mt], ka + mt * 1280);
#pragma unroll
            for (int p = 0; p < 4; p++)  ldsm4(bf[p], kb + p * 1280);
            // term hi*hi (32 MMA)
#pragma unroll
            for (int mt = 0; mt < 4; mt++)
#pragma unroll
                for (int nt = 0; nt < 8; nt++)
                    mma_bf16(acc[mt][nt], af[mt], &bf[nt >> 1][(nt & 1) * 2]);
            // term hi*lo
#pragma unroll
            for (int p = 0; p < 4; p++)  ldsm4(bf2[p], kb + GARR_B + p * 1280);
#pragma unroll
            for (int mt = 0; mt < 4; mt++)
#pragma unroll
                for (int nt = 0; nt < 8; nt++)
                    mma_bf16(acc[mt][nt], af[mt], &bf2[nt >> 1][(nt & 1) * 2]);
            // term lo*hi (af overwritten with Alo)
#pragma unroll
            for (int mt = 0; mt < 4; mt++) ldsm4(af[mt], ka + GARR_A + mt * 1280);
#pragma unroll
            for (int mt = 0; mt < 4; mt++)
#pragma unroll
                for (int nt = 0; nt < 8; nt++)
                    mma_bf16(acc[mt][nt], af[mt], &bf[nt >> 1][(nt & 1) * 2]);
        }
        __syncthreads();
        if (ck + 2 < nchunks) issue(ck + 2);
        CP_COMMIT();
    }
}

// ---------------------------------------------------------------------------
// Fused QKV GEMM: z = 0:Q, 1:K, 2:V.  CTA 128x256; each warp's 64 cols =
// exactly one head, so RoPE pairs (i, i+32) live in the same thread's
// accumulators (nt <-> nt+4): fully register-resident epilogue.
// ---------------------------------------------------------------------------
__global__ __launch_bounds__(256, 1) void gemm_qkv_kernel(
    const __nv_bfloat16* __restrict__ xh, const __nv_bfloat16* __restrict__ xl,
    const float* __restrict__ bq, const float* __restrict__ bk,
    const float* __restrict__ bv)
{
    extern __shared__ char sm[];
    const uint32_t smb = smem_u32(sm);
    const int tid = threadIdx.x;
    const int wid = tid >> 5, lid = tid & 31;
    const int bm = blockIdx.y * 128, bn = blockIdx.x * 256;
    const int z = blockIdx.z;
    const int warp_m = wid & 1, warp_n = wid >> 1;

    const __nv_bfloat16* Whi = (z == 0) ? g_Wqh : (z == 1) ? g_Wkh : g_Wvh;
    const __nv_bfloat16* Wlo = (z == 0) ? g_Wql : (z == 1) ? g_Wkl : g_Wvl;
    const float* bias = (z == 0) ? bq : (z == 1) ? bk : bv;

    float acc[4][8][4];
#pragma unroll
    for (int i = 0; i < 4; i++)
#pragma unroll
        for (int j = 0; j < 8; j++)
#pragma unroll
            for (int v = 0; v < 4; v++) acc[i][j][v] = 0.f;

    gemm_core(xh + (size_t)bm * DD, xl + (size_t)bm * DD,
              Whi + (size_t)bn * DD, Wlo + (size_t)bn * DD,
              smb, tid, wid, lid, acc);

    const int gr = lid >> 2, gc = lid & 3;

    if (z == 2) {
        // V: direct single-fp16 store (+bias)
#pragma unroll
        for (int nt = 0; nt < 8; nt++) {
            const int col = bn + warp_n * 64 + nt * 8 + gc * 2;
            const float2 bv2 = *(const float2*)(bias + col);
#pragma unroll
            for (int mt = 0; mt < 4; mt++) {
                const int row = bm + warp_m * 64 + mt * 16 + gr;
                *(uint32_t*)&g_Vh[(size_t)row * DD + col] =
                    pack_f16(acc[mt][nt][0] + bv2.x, acc[mt][nt][1] + bv2.y);
                *(uint32_t*)&g_Vh[(size_t)(row + 8) * DD + col] =
                    pack_f16(acc[mt][nt][2] + bv2.x, acc[mt][nt][3] + bv2.y);
            }
        }
        return;
    }

    // Q/K: register-resident RoPE. Partner column (i+32) is acc[mt][nt+4].
#pragma unroll
    for (int nt = 0; nt < 4; nt++) {
        const int i0 = nt * 8 + gc * 2;            // in-head index 0..30
        const int col = bn + warp_n * 64 + i0;
        const float2 blo2 = *(const float2*)(bias + col);
        const float2 bhi2 = *(const float2*)(bias + col + 32);
#pragma unroll
        for (int mt = 0; mt < 4; mt++) {
            const int row0 = bm + warp_m * 64 + mt * 16 + gr;
#pragma unroll
            for (int half = 0; half < 2; half++) {
                const int row = row0 + half * 8;
                const int s = row & (SS - 1);
                const float cs0 = g_cos[s * 32 + i0], sn0 = g_sin[s * 32 + i0];
                const float cs1 = g_cos[s * 32 + i0 + 1], sn1 = g_sin[s * 32 + i0 + 1];
                const float v1a = acc[mt][nt][half * 2]     + blo2.x;
                const float v1b = acc[mt][nt][half * 2 + 1] + blo2.y;
                const float v2a = acc[mt][nt + 4][half * 2]     + bhi2.x;
                const float v2b = acc[mt][nt + 4][half * 2 + 1] + bhi2.y;
                const float r1a = v1a * cs0 - v2a * sn0;
                const float r2a = v2a * cs0 + v1a * sn0;
                const float r1b = v1b * cs1 - v2b * sn1;
                const float r2b = v2b * cs1 + v1b * sn1;
                const size_t out = (size_t)row * DD + col;
                if (z == 0) {
                    *(uint32_t*)&g_Qh[out]      = pack_f16(r1a * QSC, r1b * QSC);
                    *(uint32_t*)&g_Qh[out + 32] = pack_f16(r2a * QSC, r2b * QSC);
                } else {
                    *(uint32_t*)&g_Kh[out]      = pack_f16(r1a, r1b);
                    *(uint32_t*)&g_Kh[out + 32] = pack_f16(r2a, r2b);
                }
            }
        }
    }
}

// ---------------------------------------------------------------------------
// O-projection GEMM: out = A @ Wo^T + bo, fp32 out. CTA 128x256.
// ---------------------------------------------------------------------------
__global__ __launch_bounds__(256, 1) void gemm_o_kernel(
    const float* __restrict__ bias, float* __restrict__ C)
{
    extern __shared__ char sm[];
    const uint32_t smb = smem_u32(sm);
    const int tid = threadIdx.x;
    const int wid = tid >> 5, lid = tid & 31;
    const int bm = blockIdx.y * 128, bn = blockIdx.x * 256;
    const int warp_m = wid & 1, warp_n = wid >> 1;

    float acc[4][8][4];
#pragma unroll
    for (int i = 0; i < 4; i++)
#pragma unroll
        for (int j = 0; j < 8; j++)
#pragma unroll
            for (int v = 0; v < 4; v++) acc[i][j][v] = 0.f;

    gemm_core(g_Ahi + (size_t)bm * DD, g_Alo + (size_t)bm * DD,
              g_Woh + (size_t)bn * DD, g_Wol + (size_t)bn * DD,
              smb, tid, wid, lid, acc);

    const int gr = lid >> 2, gc = lid & 3;
#pragma unroll
    for (int nt = 0; nt < 8; nt++) {
        const int col = bn + warp_n * 64 + nt * 8 + gc * 2;
        const float2 bv = *(const float2*)(bias + col);
#pragma unroll
        for (int mt = 0; mt < 4; mt++) {
            const int row = bm + warp_m * 64 + mt * 16 + gr;
            *(float2*)(C + (size_t)row * DD + col) =
                make_float2(acc[mt][nt][0] + bv.x, acc[mt][nt][1] + bv.y);
            *(float2*)(C + (size_t)(row + 8) * DD + col) =
                make_float2(acc[mt][nt][2] + bv.x, acc[mt][nt][3] + bv.y);
        }
    }
}

// ---------------------------------------------------------------------------
// HMMA causal flash attention, all-single-fp16 operands.
// BR=128 (8 warps x 16 rows), BC=64. 64 MMAs/tile/warp. 4-deep cp.async.
// Now 2 CTAs/SM (92 KB x 2 smem, 128-reg cap) for latency hiding.
// ---------------------------------------------------------------------------
#define AQ_B   18432            // 128*144
#define AARR_B 9216             // 64*144
#define ASTG_B (2 * AARR_B)     // 18432
#define ASMEM_TOTAL (AQ_B + 4 * ASTG_B)   // 92160

__global__ __launch_bounds__(256, 2) void attn_mma_kernel()
{
    extern __shared__ char sm[];
    const uint32_t smb = smem_u32(sm);
    const int tid = threadIdx.x;
    const int w = tid >> 5, lane = tid & 31;
    const int gr = lane >> 2, gc = lane & 3;
    const int qt = (int)gridDim.x - 1 - (int)blockIdx.x;   // long blocks first
    const int h = blockIdx.y, b = blockIdx.z;

    const size_t hb = ((size_t)b * SS) * DD + (size_t)h * HDIM;
    const size_t qrow0 = (size_t)qt * 128;

    const int ntiles = 2 * qt + 2;

    // --- prologue: Q tile (single fp16) ---
#pragma unroll
    for (int i = 0; i < 4; i++) {
        int idx = tid + i * 256;          // 1024 chunks
        int row = idx >> 3, c = idx & 7;
        cp16(smb + row * 144 + c * 16, g_Qh + hb + (qrow0 + row) * DD + c * 8);
    }
    CP_COMMIT();

    auto stage_load = [&](int jt, int s) {
        const uint32_t base = smb + AQ_B + (uint32_t)s * ASTG_B;
#pragma unroll
        for (int i = 0; i < 2; i++) {
            int idx = tid + i * 256;       // 512 chunks per array
            int row = idx >> 3, c = idx & 7;
            cp16(base + row * 144 + c * 16,
                 g_Kh + hb + (size_t)(jt * 64 + row) * DD + c * 8);
            cp16(base + AARR_B + row * 144 + c * 16,
                 g_Vh + hb + (size_t)(jt * 64 + row) * DD + c * 8);
        }
    };
    stage_load(0, 0); CP_COMMIT();
    if (1 < ntiles) stage_load(1, 1);
    CP_COMMIT();
    if (2 < ntiles) stage_load(2, 2);
    CP_COMMIT();

    float m0 = -1e30f, m1 = -1e30f, l0 = 0.f, l1 = 0.f;
    float o[8][4];
#pragma unroll
    for (int d = 0; d < 8; d++)
#pragma unroll
        for (int v = 0; v < 4; v++) o[d][v] = 0.f;

    uint32_t aQ[4][4];
    const int qrow_lo = qt * 128 + w * 16 + gr;

    for (int jt = 0; jt < ntiles; jt++) {
        CP_WAIT(2);
        __syncthreads();
        if (jt + 3 < ntiles) stage_load(jt + 3, (jt + 3) & 3);
        CP_COMMIT();

        if (jt == 0) {   // Q fragments (loop-invariant; Q group completed)
            const uint32_t qa = smb + (uint32_t)(w * 16 + (lane & 15)) * 144
                                + (lane >> 4) * 16;
#pragma unroll
            for (int kt = 0; kt < 4; kt++) ldsm4(aQ[kt], qa + kt * 32);
        }

        const uint32_t stg = smb + AQ_B + (uint32_t)(jt & 3) * ASTG_B;

        // ---- S = Q K^T (single fp16) ----
        float sc[8][4];
#pragma unroll
        for (int nt = 0; nt < 8; nt++)
#pragma unroll
            for (int v = 0; v < 4; v++) sc[nt][v] = 0.f;

        const uint32_t kaddr = stg
            + (uint32_t)((lane & 7) | ((lane & 16) >> 1)) * 144 + (lane & 8) * 2;
#pragma unroll
        for (int kt = 0; kt < 4; kt++) {
            uint32_t bK[4][4];
#pragma unroll
            for (int np = 0; np < 4; np++)
                ldsm4(bK[np], kaddr + np * 2304 + kt * 32);
#pragma unroll
            for (int np = 0; np < 4; np++) {
                mma_f16(sc[2*np],   aQ[kt], &bK[np][0]);
                mma_f16(sc[2*np+1], aQ[kt], &bK[np][2]);
            }
        }

        // ---- causal mask (only last two tiles) ----
        if (jt >= 2 * qt) {
#pragma unroll
            for (int nt = 0; nt < 8; nt++) {
                int j = jt * 64 + nt * 8 + gc * 2;
                if (j     > qrow_lo)     sc[nt][0] = -1e30f;
                if (j + 1 > qrow_lo)     sc[nt][1] = -1e30f;
                if (j     > qrow_lo + 8) sc[nt][2] = -1e30f;
                if (j + 1 > qrow_lo + 8) sc[nt][3] = -1e30f;
            }
        }

        // ---- online softmax (exp2 domain) ----
        float mx0 = -1e30f, mx1 = -1e30f;
#pragma unroll
        for (int nt = 0; nt < 8; nt++) {
            mx0 = fmaxf(mx0, fmaxf(sc[nt][0], sc[nt][1]));
            mx1 = fmaxf(mx1, fmaxf(sc[nt][2], sc[nt][3]));
        }
        mx0 = fmaxf(mx0, __shfl_xor_sync(0xffffffffu, mx0, 1));
        mx0 = fmaxf(mx0, __shfl_xor_sync(0xffffffffu, mx0, 2));
        mx1 = fmaxf(mx1, __shfl_xor_sync(0xffffffffu, mx1, 1));
        mx1 = fmaxf(mx1, __shfl_xor_sync(0xffffffffu, mx1, 2));

        float mn0 = fmaxf(m0, mx0), mn1 = fmaxf(m1, mx1);
        float al0 = exp2f(m0 - mn0), al1 = exp2f(m1 - mn1);
        m0 = mn0; m1 = mn1;

        float rs0 = 0.f, rs1 = 0.f;
#pragma unroll
        for (int nt = 0; nt < 8; nt++) {
            sc[nt][0] = exp2f(sc[nt][0] - mn0);
            sc[nt][1] = exp2f(sc[nt][1] - mn0);
            sc[nt][2] = exp2f(sc[nt][2] - mn1);
            sc[nt][3] = exp2f(sc[nt][3] - mn1);
            rs0 += sc[nt][0] + sc[nt][1];
            rs1 += sc[nt][2] + sc[nt][3];
        }
        rs0 += __shfl_xor_sync(0xffffffffu, rs0, 1);
        rs0 += __shfl_xor_sync(0xffffffffu, rs0, 2);
        rs1 += __shfl_xor_sync(0xffffffffu, rs1, 1);
        rs1 += __shfl_xor_sync(0xffffffffu, rs1, 2);
        l0 = l0 * al0 + rs0;
        l1 = l1 * al1 + rs1;
#pragma unroll
        for (int d = 0; d < 8; d++) {
            o[d][0] *= al0; o[d][1] *= al0;
            o[d][2] *= al1; o[d][3] *= al1;
        }

        // ---- O += P V (single fp16; P in registers) ----
        const uint32_t vaddr = stg + AARR_B
            + (uint32_t)(lane & 15) * 144 + (lane >> 4) * 16;
#pragma unroll
        for (int kt = 0; kt < 4; kt++) {
            uint32_t aP[4];
            aP[0] = pack_f16(sc[2*kt][0],   sc[2*kt][1]);
            aP[1] = pack_f16(sc[2*kt][2],   sc[2*kt][3]);
            aP[2] = pack_f16(sc[2*kt+1][0], sc[2*kt+1][1]);
            aP[3] = pack_f16(sc[2*kt+1][2], sc[2*kt+1][3]);

            uint32_t bV[4][4];
#pragma unroll
            for (int dp = 0; dp < 4; dp++)
                ldsm4t(bV[dp], vaddr + kt * 2304 + dp * 32);
#pragma unroll
            for (int dp = 0; dp < 4; dp++) {
                mma_f16(o[2*dp],   aP, &bV[dp][0]);
                mma_f16(o[2*dp+1], aP, &bV[dp][2]);
            }
        }
    }

    // ---- epilogue: /l, split to bf16 hi/lo for O-projection ----
    const float inv0 = 1.0f / l0, inv1 = 1.0f / l1;
#pragma unroll
    for (int dt = 0; dt < 8; dt++) {
        size_t idx = hb + (qrow0 + w * 16 + gr) * DD + dt * 8 + gc * 2;
        uint32_t hh, ll;
        cvt_split2(o[dt][0] * inv0, o[dt][1] * inv0, hh, ll);
        *(uint32_t*)&g_Ahi[idx] = hh;
        *(uint32_t*)&g_Alo[idx] = ll;
        size_t idx8 = idx + 8 * DD;
        cvt_split2(o[dt][2] * inv1, o[dt][3] * inv1, hh, ll);
        *(uint32_t*)&g_Ahi[idx8] = hh;
        *(uint32_t*)&g_Alo[idx8] = ll;
    }
}

// ---------------------------------------------------------------------------
extern "C" void kernel_launch(void* const* d_in, const int* in_sizes, int n_in,
                              void* d_out, int out_size)
{
    (void)in_sizes; (void)n_in; (void)out_size;
    const float* x  = (const float*)d_in[0];
    const float* Wq = (const float*)d_in[1];
    const float* bq = (const float*)d_in[2];
    const float* Wk = (const float*)d_in[3];
    const float* bk = (const float*)d_in[4];
    const float* Wv = (const float*)d_in[5];
    const float* bv = (const float*)d_in[6];
    const float* Wo = (const float*)d_in[7];
    const float* bo = (const float*)d_in[8];
    float* out = (float*)d_out;

    __nv_bfloat16 *xh, *xl;
    cudaGetSymbolAddress((void**)&xh, g_xhi);
    cudaGetSymbolAddress((void**)&xl, g_xlo);

    cudaFuncSetAttribute(gemm_qkv_kernel,
                         cudaFuncAttributeMaxDynamicSharedMemorySize, GSMEM_TOTAL);
    cudaFuncSetAttribute(gemm_o_kernel,
                         cudaFuncAttributeMaxDynamicSharedMemorySize, GSMEM_TOTAL);
    cudaFuncSetAttribute(attn_mma_kernel,
                         cudaFuncAttributeMaxDynamicSharedMemorySize, ASMEM_TOTAL);

    prep_kernel<<<12544, 256>>>(x, Wq, Wk, Wv, Wo);

    gemm_qkv_kernel<<<dim3(DD / 256, MM / 128, 3), 256, GSMEM_TOTAL>>>(
        xh, xl, bq, bk, bv);

    attn_mma_kernel<<<dim3(SS / 128, HH, BB), 256, ASMEM_TOTAL>>>();

    gemm_o_kernel<<<dim3(DD / 256, MM / 128), 256, GSMEM_TOTAL>>>(bo, out);
}

// round 12
// speedup vs baseline: 1.1084x; 1.1084x over previous
#include <cuda_runtime.h>
#include <cuda_bf16.h>
#include <cuda_fp16.h>
#include <cstdint>

// Problem constants
#define BB 4
#define SS 2048
#define DD 1024
#define HH 16
#define HDIM 64
#define MM (BB * SS)   // 8192

// log2(e) * 0.125 (softmax scale folded into Q, exp2 domain)
#define QSC 0.18033688011112042f

// ---------------------------------------------------------------------------
// Device-global scratch (allocation-free rule)
// ---------------------------------------------------------------------------
__device__ __nv_bfloat16 g_xhi[(size_t)MM * DD], g_xlo[(size_t)MM * DD];
__device__ __nv_bfloat16 g_Wqh[DD * DD], g_Wql[DD * DD];
__device__ __nv_bfloat16 g_Wkh[DD * DD], g_Wkl[DD * DD];
__device__ __nv_bfloat16 g_Wvh[DD * DD], g_Wvl[DD * DD];
__device__ __nv_bfloat16 g_Woh[DD * DD], g_Wol[DD * DD];
__device__ __half g_Qh[(size_t)MM * DD];    // single fp16 (scaled)
__device__ __half g_Kh[(size_t)MM * DD];    // single fp16
__device__ __half g_Vh[(size_t)MM * DD];    // single fp16
__device__ __nv_bfloat16 g_Ahi[(size_t)MM * DD], g_Alo[(size_t)MM * DD];
__device__ float g_cos[SS * 32];
__device__ float g_sin[SS * 32];

// ---------------------------------------------------------------------------
// PTX helpers (portable sm_80+: ldmatrix, mma.sync, cp.async)
// ---------------------------------------------------------------------------
__device__ __forceinline__ uint32_t smem_u32(const void* p) {
    uint32_t a;
    asm("{ .reg .u64 t; cvta.to.shared.u64 t, %1; cvt.u32.u64 %0, t; }"
        : "=r"(a) : "l"(p));
    return a;
}

__device__ __forceinline__ void ldsm4(uint32_t* r, uint32_t addr) {
    asm volatile("ldmatrix.sync.aligned.m8n8.x4.shared.b16 {%0,%1,%2,%3}, [%4];"
        : "=r"(r[0]), "=r"(r[1]), "=r"(r[2]), "=r"(r[3]) : "r"(addr));
}

__device__ __forceinline__ void ldsm4t(uint32_t* r, uint32_t addr) {
    asm volatile("ldmatrix.sync.aligned.m8n8.x4.trans.shared.b16 {%0,%1,%2,%3}, [%4];"
        : "=r"(r[0]), "=r"(r[1]), "=r"(r[2]), "=r"(r[3]) : "r"(addr));
}

__device__ __forceinline__ void mma_bf16(float* c, const uint32_t* a, const uint32_t* b) {
    asm volatile(
        "mma.sync.aligned.m16n8k16.row.col.f32.bf16.bf16.f32 "
        "{%0,%1,%2,%3}, {%4,%5,%6,%7}, {%8,%9}, {%0,%1,%2,%3};"
        : "+f"(c[0]), "+f"(c[1]), "+f"(c[2]), "+f"(c[3])
        : "r"(a[0]), "r"(a[1]), "r"(a[2]), "r"(a[3]), "r"(b[0]), "r"(b[1]));
}

__device__ __forceinline__ void mma_f16(float* c, const uint32_t* a, const uint32_t* b) {
    asm volatile(
        "mma.sync.aligned.m16n8k16.row.col.f32.f16.f16.f32 "
        "{%0,%1,%2,%3}, {%4,%5,%6,%7}, {%8,%9}, {%0,%1,%2,%3};"
        : "+f"(c[0]), "+f"(c[1]), "+f"(c[2]), "+f"(c[3])
        : "r"(a[0]), "r"(a[1]), "r"(a[2]), "r"(a[3]), "r"(b[0]), "r"(b[1]));
}

__device__ __forceinline__ void cp16(uint32_t dst, const void* src) {
    asm volatile("cp.async.cg.shared.global [%0], [%1], 16;" :: "r"(dst), "l"(src));
}
#define CP_COMMIT() asm volatile("cp.async.commit_group;" ::: "memory")
#define CP_WAIT(n)  asm volatile("cp.async.wait_group %0;" :: "n"(n) : "memory")

// fp32 pair -> packed bf16x2 hi + bf16x2 lo (residual)
__device__ __forceinline__ void cvt_split2(float v0, float v1, uint32_t& h, uint32_t& l) {
    asm("cvt.rn.bf16x2.f32 %0, %1, %2;" : "=r"(h) : "f"(v1), "f"(v0));
    float r0 = v0 - __uint_as_float(h << 16);
    float r1 = v1 - __uint_as_float(h & 0xffff0000u);
    asm("cvt.rn.bf16x2.f32 %0, %1, %2;" : "=r"(l) : "f"(r1), "f"(r0));
}

// fp32 pair -> packed f16x2 (lo half = v0)
__device__ __forceinline__ uint32_t pack_f16(float v0, float v1) {
    uint32_t r;
    asm("cvt.rn.f16x2.f32 %0, %1, %2;" : "=r"(r) : "f"(v1), "f"(v0));
    return r;
}

// ---------------------------------------------------------------------------
// Fused prep: rope tables + x split + 4 weight splits, one launch.
// blocks [0,8192) = x, [8192,12288) = weights (1024 each), [12288,12544) = rope
// ---------------------------------------------------------------------------
__global__ __launch_bounds__(256) void prep_kernel(
    const float* __restrict__ x,
    const float* __restrict__ Wq, const float* __restrict__ Wk,
    const float* __restrict__ Wv, const float* __restrict__ Wo)
{
    const int bid = blockIdx.x;
    const int tid = threadIdx.x;

    if (bid < 8192) {                       // x: 2097152 float4 chunks
        int i = bid * 256 + tid;
        float4 v = ((const float4*)x)[i];
        uint32_t h01, h23, l01, l23;
        cvt_split2(v.x, v.y, h01, l01);
        cvt_split2(v.z, v.w, h23, l23);
        ((uint2*)g_xhi)[i] = make_uint2(h01, h23);
        ((uint2*)g_xlo)[i] = make_uint2(l01, l23);
    } else if (bid < 12288) {               // weights
        int wb = bid - 8192;
        int z = wb >> 10;
        const float* src = (z == 0) ? Wq : (z == 1) ? Wk : (z == 2) ? Wv : Wo;
        __nv_bfloat16* hi = (z == 0) ? g_Wqh : (z == 1) ? g_Wkh : (z == 2) ? g_Wvh : g_Woh;
        __nv_bfloat16* lo = (z == 0) ? g_Wql : (z == 1) ? g_Wkl : (z == 2) ? g_Wvl : g_Wol;
        int i = (wb & 1023) * 256 + tid;
        float4 v = ((const float4*)src)[i];
        uint32_t h01, h23, l01, l23;
        cvt_split2(v.x, v.y, h01, l01);
        cvt_split2(v.z, v.w, h23, l23);
        ((uint2*)hi)[i] = make_uint2(h01, h23);
        ((uint2*)lo)[i] = make_uint2(l01, l23);
    } else {                                // rope tables: S*32 entries
        int idx = (bid - 12288) * 256 + tid;
        int i = idx & 31;
        int s = idx >> 5;
        double inv_freq = exp((double)i * -0.28782313662425575);  // -ln(10000)/32
        double sd, cd;
        sincos((double)s * inv_freq, &sd, &cd);
        g_cos[idx] = (float)cd;
        g_sin[idx] = (float)sd;
    }
}

// ---------------------------------------------------------------------------
// GEMM core (bf16 3-term): 128x128 CTA, 8 warps (64x32), K-chunk 32,
// 2-stage cp.async pipeline, 80 KB smem => 2 CTAs/SM (128 regs cap).
// Inner loop term-sequenced with register reuse: af holds hi for hh+hl
// terms, then is overwritten with lo for the lh term. Per-acc accumulation
// order unchanged (hh -> hl -> lh per kk) => bit-exact vs R8/R9/R10.
// Stage (40960B): Ahi[128x80] | Alo | Whi | Wlo
// ---------------------------------------------------------------------------
#define GARR   10240            // 128 * 80
#define GSTAGE 40960
#define GSMEM_TOTAL (2 * GSTAGE)   // 81920

__device__ __forceinline__ void gemm_core(
    const __nv_bfloat16* const* srcs, uint32_t smb,
    int tid, int wid, int lid, float acc[4][4][4])
{
    const int warp_m = wid & 1, warp_n = wid >> 1;
    const int arow = lid & 15;
    const int ak16 = (lid & 16);
    const int brow = (lid & 7) | ((lid & 16) >> 1);
    const int bk16 = (lid & 8) * 2;
    const uint32_t aBase = smb + (uint32_t)(warp_m * 64 + arow) * 80 + ak16;
    const uint32_t bBase = smb + 2 * GARR
        + (uint32_t)(warp_n * 32 + brow) * 80 + bk16;

    auto issue = [&](int ck) {
        const uint32_t base = smb + (uint32_t)(ck & 1) * GSTAGE;
        const int k0 = ck * 32;
#pragma unroll
        for (int a = 0; a < 4; a++) {
#pragma unroll
            for (int i = 0; i < 2; i++) {
                int idx = tid + i * 256;        // 512 chunks per array
                int row = idx >> 2, q = idx & 3;
                cp16(base + a * GARR + row * 80 + q * 16,
                     srcs[a] + (size_t)row * DD + k0 + q * 8);
            }
        }
    };

    issue(0); CP_COMMIT();
    issue(1); CP_COMMIT();

    const int nchunks = DD / 32;   // 32
    for (int ck = 0; ck < nchunks; ck++) {
        CP_WAIT(1);
        __syncthreads();

        const uint32_t bo = (uint32_t)(ck & 1) * GSTAGE;
#pragma unroll
        for (int kk = 0; kk < 2; kk++) {
            uint32_t af[4][4], bf[2][4], bf2[2][4];
            const uint32_t ka = aBase + bo + kk * 32;
            const uint32_t kb = bBase + bo + kk * 32;
            // hi operands
#pragma unroll
            for (int mt = 0; mt < 4; mt++) ldsm4(af[mt], ka + mt * 1280);
#pragma unroll
            for (int p = 0; p < 2; p++)  ldsm4(bf[p], kb + p * 1280);
            // term hi*hi
#pragma unroll
            for (int mt = 0; mt < 4; mt++)
#pragma unroll
                for (int nt = 0; nt < 4; nt++)
                    mma_bf16(acc[mt][nt], af[mt], &bf[nt >> 1][(nt & 1) * 2]);
            // term hi*lo
#pragma unroll
            for (int p = 0; p < 2; p++)  ldsm4(bf2[p], kb + GARR + p * 1280);
#pragma unroll
            for (int mt = 0; mt < 4; mt++)
#pragma unroll
                for (int nt = 0; nt < 4; nt++)
                    mma_bf16(acc[mt][nt], af[mt], &bf2[nt >> 1][(nt & 1) * 2]);
            // term lo*hi (af overwritten with Alo)
#pragma unroll
            for (int mt = 0; mt < 4; mt++) ldsm4(af[mt], ka + GARR + mt * 1280);
#pragma unroll
            for (int mt = 0; mt < 4; mt++)
#pragma unroll
                for (int nt = 0; nt < 4; nt++)
                    mma_bf16(acc[mt][nt], af[mt], &bf[nt >> 1][(nt & 1) * 2]);
        }
        __syncthreads();
        if (ck + 2 < nchunks) issue(ck + 2);
        CP_COMMIT();
    }
}

// ---------------------------------------------------------------------------
// Fused QKV GEMM: z = 0:Q, 1:K, 2:V.  Epilogue fuses RoPE + fp16 store.
// ---------------------------------------------------------------------------
__global__ __launch_bounds__(256, 2) void gemm_qkv_kernel(
    const __nv_bfloat16* __restrict__ xh, const __nv_bfloat16* __restrict__ xl,
    const float* __restrict__ bq, const float* __restrict__ bk,
    const float* __restrict__ bv)
{
    extern __shared__ char sm[];
    const uint32_t smb = smem_u32(sm);
    const int tid = threadIdx.x;
    const int wid = tid >> 5, lid = tid & 31;
    const int bm = blockIdx.y * 128, bn = blockIdx.x * 128;
    const int z = blockIdx.z;
    const int warp_m = wid & 1, warp_n = wid >> 1;

    const __nv_bfloat16* Whi = (z == 0) ? g_Wqh : (z == 1) ? g_Wkh : g_Wvh;
    const __nv_bfloat16* Wlo = (z == 0) ? g_Wql : (z == 1) ? g_Wkl : g_Wvl;
    const float* bias = (z == 0) ? bq : (z == 1) ? bk : bv;

    const __nv_bfloat16* srcs[4] = {
        xh + (size_t)bm * DD, xl + (size_t)bm * DD,
        Whi + (size_t)bn * DD, Wlo + (size_t)bn * DD };

    float acc[4][4][4];
#pragma unroll
    for (int i = 0; i < 4; i++)
#pragma unroll
        for (int j = 0; j < 4; j++)
#pragma unroll
            for (int v = 0; v < 4; v++) acc[i][j][v] = 0.f;

    gemm_core(srcs, smb, tid, wid, lid, acc);

    const int gr = lid >> 2, gc = lid & 3;

    if (z == 2) {
        // V: direct single-fp16 store (+bias)
#pragma unroll
        for (int nt = 0; nt < 4; nt++) {
            const int col = bn + warp_n * 32 + nt * 8 + gc * 2;
            const float2 bv2 = *(const float2*)(bias + col);
#pragma unroll
            for (int mt = 0; mt < 4; mt++) {
                const int row = bm + warp_m * 64 + mt * 16 + gr;
                *(uint32_t*)&g_Vh[(size_t)row * DD + col] =
                    pack_f16(acc[mt][nt][0] + bv2.x, acc[mt][nt][1] + bv2.y);
                *(uint32_t*)&g_Vh[(size_t)(row + 8) * DD + col] =
                    pack_f16(acc[mt][nt][2] + bv2.x, acc[mt][nt][3] + bv2.y);
            }
        }
        return;
    }

    // Q/K: stage to smem (+bias), then RoPE across (i, i+32) pairs.
    CP_WAIT(0);
    __syncthreads();
    float* Ds = (float*)sm;    // [128][132] = 67584 B < 81920
#pragma unroll
    for (int nt = 0; nt < 4; nt++) {
        const int cl = warp_n * 32 + nt * 8 + gc * 2;
        const float2 bv2 = *(const float2*)(bias + bn + cl);
#pragma unroll
        for (int mt = 0; mt < 4; mt++) {
            const int rl = warp_m * 64 + mt * 16 + gr;
            Ds[rl * 132 + cl]     = acc[mt][nt][0] + bv2.x;
            Ds[rl * 132 + cl + 1] = acc[mt][nt][1] + bv2.y;
            Ds[(rl + 8) * 132 + cl]     = acc[mt][nt][2] + bv2.x;
            Ds[(rl + 8) * 132 + cl + 1] = acc[mt][nt][3] + bv2.y;
        }
    }
    __syncthreads();

    for (int u = tid; u < 128 * 32; u += 256) {
        const int row = u >> 5, t = u & 31;
        const int hl = t >> 4, tt = t & 15;
        const int col = hl * 64 + tt * 2;
        const int s = (bm + row) & (SS - 1);
        const int i0 = tt * 2;
        const float cs0 = g_cos[s * 32 + i0], sn0 = g_sin[s * 32 + i0];
        const float cs1 = g_cos[s * 32 + i0 + 1], sn1 = g_sin[s * 32 + i0 + 1];
        const float v1a = Ds[row * 132 + col],      v1b = Ds[row * 132 + col + 1];
        const float v2a = Ds[row * 132 + col + 32], v2b = Ds[row * 132 + col + 33];
        const float r1a = v1a * cs0 - v2a * sn0, r2a = v2a * cs0 + v1a * sn0;
        const float r1b = v1b * cs1 - v2b * sn1, r2b = v2b * cs1 + v1b * sn1;
        const size_t out = (size_t)(bm + row) * DD + bn + col;
        if (z == 0) {
            *(uint32_t*)&g_Qh[out]      = pack_f16(r1a * QSC, r1b * QSC);
            *(uint32_t*)&g_Qh[out + 32] = pack_f16(r2a * QSC, r2b * QSC);
        } else {
            *(uint32_t*)&g_Kh[out]      = pack_f16(r1a, r1b);
            *(uint32_t*)&g_Kh[out + 32] = pack_f16(r2a, r2b);
        }
    }
}

// ---------------------------------------------------------------------------
// O-projection GEMM: out = A @ Wo^T + bo, fp32 out.
// ---------------------------------------------------------------------------
__global__ __launch_bounds__(256, 2) void gemm_o_kernel(
    const float* __restrict__ bias, float* __restrict__ C)
{
    extern __shared__ char sm[];
    const uint32_t smb = smem_u32(sm);
    const int tid = threadIdx.x;
    const int wid = tid >> 5, lid = tid & 31;
    const int bm = blockIdx.y * 128, bn = blockIdx.x * 128;
    const int warp_m = wid & 1, warp_n = wid >> 1;

    const __nv_bfloat16* srcs[4] = {
        g_Ahi + (size_t)bm * DD, g_Alo + (size_t)bm * DD,
        g_Woh + (size_t)bn * DD, g_Wol + (size_t)bn * DD };

    float acc[4][4][4];
#pragma unroll
    for (int i = 0; i < 4; i++)
#pragma unroll
        for (int j = 0; j < 4; j++)
#pragma unroll
            for (int v = 0; v < 4; v++) acc[i][j][v] = 0.f;

    gemm_core(srcs, smb, tid, wid, lid, acc);

    const int gr = lid >> 2, gc = lid & 3;
#pragma unroll
    for (int nt = 0; nt < 4; nt++) {
        const int col = bn + warp_n * 32 + nt * 8 + gc * 2;
        const float2 bv = *(const float2*)(bias + col);
#pragma unroll
        for (int mt = 0; mt < 4; mt++) {
            const int row = bm + warp_m * 64 + mt * 16 + gr;
            *(float2*)(C + (size_t)row * DD + col) =
                make_float2(acc[mt][nt][0] + bv.x, acc[mt][nt][1] + bv.y);
            *(float2*)(C + (size_t)(row + 8) * DD + col) =
                make_float2(acc[mt][nt][2] + bv.x, acc[mt][nt][3] + bv.y);
        }
    }
}

// ---------------------------------------------------------------------------
// HMMA causal flash attention, all-single-fp16 operands.
// BR=128 (8 warps x 16 rows), BC=64. 64 MMAs/tile/warp. 4-deep cp.async.
// 2 CTAs/SM (92 KB x 2 smem fits) for latency hiding across softmax chains.
// ---------------------------------------------------------------------------
#define AQ_B   18432            // 128*144
#define AARR_B 9216             // 64*144
#define ASTG_B (2 * AARR_B)     // 18432
#define ASMEM_TOTAL (AQ_B + 4 * ASTG_B)   // 92160

__global__ __launch_bounds__(256, 2) void attn_mma_kernel()
{
    extern __shared__ char sm[];
    const uint32_t smb = smem_u32(sm);
    const int tid = threadIdx.x;
    const int w = tid >> 5, lane = tid & 31;
    const int gr = lane >> 2, gc = lane & 3;
    const int qt = (int)gridDim.x - 1 - (int)blockIdx.x;   // long blocks first
    const int h = blockIdx.y, b = blockIdx.z;

    const size_t hb = ((size_t)b * SS) * DD + (size_t)h * HDIM;
    const size_t qrow0 = (size_t)qt * 128;

    const int ntiles = 2 * qt + 2;

    // --- prologue: Q tile (single fp16) ---
#pragma unroll
    for (int i = 0; i < 4; i++) {
        int idx = tid + i * 256;          // 1024 chunks
        int row = idx >> 3, c = idx & 7;
        cp16(smb + row * 144 + c * 16, g_Qh + hb + (qrow0 + row) * DD + c * 8);
    }
    CP_COMMIT();

    auto stage_load = [&](int jt, int s) {
        const uint32_t base = smb + AQ_B + (uint32_t)s * ASTG_B;
#pragma unroll
        for (int i = 0; i < 2; i++) {
            int idx = tid + i * 256;       // 512 chunks per array
            int row = idx >> 3, c = idx & 7;
            cp16(base + row * 144 + c * 16,
                 g_Kh + hb + (size_t)(jt * 64 + row) * DD + c * 8);
            cp16(base + AARR_B + row * 144 + c * 16,
                 g_Vh + hb + (size_t)(jt * 64 + row) * DD + c * 8);
        }
    };
    stage_load(0, 0); CP_COMMIT();
    if (1 < ntiles) stage_load(1, 1);
    CP_COMMIT();
    if (2 < ntiles) stage_load(2, 2);
    CP_COMMIT();

    float m0 = -1e30f, m1 = -1e30f, l0 = 0.f, l1 = 0.f;
    float o[8][4];
#pragma unroll
    for (int d = 0; d < 8; d++)
#pragma unroll
        for (int v = 0; v < 4; v++) o[d][v] = 0.f;

    uint32_t aQ[4][4];
    const int qrow_lo = qt * 128 + w * 16 + gr;

    for (int jt = 0; jt < ntiles; jt++) {
        CP_WAIT(2);
        __syncthreads();
        if (jt + 3 < ntiles) stage_load(jt + 3, (jt + 3) & 3);
        CP_COMMIT();

        if (jt == 0) {   // Q fragments (loop-invariant; Q group completed)
            const uint32_t qa = smb + (uint32_t)(w * 16 + (lane & 15)) * 144
                                + (lane >> 4) * 16;
#pragma unroll
            for (int kt = 0; kt < 4; kt++) ldsm4(aQ[kt], qa + kt * 32);
        }

        const uint32_t stg = smb + AQ_B + (uint32_t)(jt & 3) * ASTG_B;

        // ---- S = Q K^T (single fp16) ----
        float sc[8][4];
#pragma unroll
        for (int nt = 0; nt < 8; nt++)
#pragma unroll
            for (int v = 0; v < 4; v++) sc[nt][v] = 0.f;

        const uint32_t kaddr = stg
            + (uint32_t)((lane & 7) | ((lane & 16) >> 1)) * 144 + (lane & 8) * 2;
#pragma unroll
        for (int kt = 0; kt < 4; kt++) {
            uint32_t bK[4][4];
#pragma unroll
            for (int np = 0; np < 4; np++)
                ldsm4(bK[np], kaddr + np * 2304 + kt * 32);
#pragma unroll
            for (int np = 0; np < 4; np++) {
                mma_f16(sc[2*np],   aQ[kt], &bK[np][0]);
                mma_f16(sc[2*np+1], aQ[kt], &bK[np][2]);
            }
        }

        // ---- causal mask (only last two tiles) ----
        if (jt >= 2 * qt) {
#pragma unroll
            for (int nt = 0; nt < 8; nt++) {
                int j = jt * 64 + nt * 8 + gc * 2;
                if (j     > qrow_lo)     sc[nt][0] = -1e30f;
                if (j + 1 > qrow_lo)     sc[nt][1] = -1e30f;
                if (j     > qrow_lo + 8) sc[nt][2] = -1e30f;
                if (j + 1 > qrow_lo + 8) sc[nt][3] = -1e30f;
            }
        }

        // ---- online softmax (exp2 domain) ----
        float mx0 = -1e30f, mx1 = -1e30f;
#pragma unroll
        for (int nt = 0; nt < 8; nt++) {
            mx0 = fmaxf(mx0, fmaxf(sc[nt][0], sc[nt][1]));
            mx1 = fmaxf(mx1, fmaxf(sc[nt][2], sc[nt][3]));
        }
        mx0 = fmaxf(mx0, __shfl_xor_sync(0xffffffffu, mx0, 1));
        mx0 = fmaxf(mx0, __shfl_xor_sync(0xffffffffu, mx0, 2));
        mx1 = fmaxf(mx1, __shfl_xor_sync(0xffffffffu, mx1, 1));
        mx1 = fmaxf(mx1, __shfl_xor_sync(0xffffffffu, mx1, 2));

        float mn0 = fmaxf(m0, mx0), mn1 = fmaxf(m1, mx1);
        float al0 = exp2f(m0 - mn0), al1 = exp2f(m1 - mn1);
        m0 = mn0; m1 = mn1;

        float rs0 = 0.f, rs1 = 0.f;
#pragma unroll
        for (int nt = 0; nt < 8; nt++) {
            sc[nt][0] = exp2f(sc[nt][0] - mn0);
            sc[nt][1] = exp2f(sc[nt][1] - mn0);
            sc[nt][2] = exp2f(sc[nt][2] - mn1);
            sc[nt][3] = exp2f(sc[nt][3] - mn1);
            rs0 += sc[nt][0] + sc[nt][1];
            rs1 += sc[nt][2] + sc[nt][3];
        }
        rs0 += __shfl_xor_sync(0xffffffffu, rs0, 1);
        rs0 += __shfl_xor_sync(0xffffffffu, rs0, 2);
        rs1 += __shfl_xor_sync(0xffffffffu, rs1, 1);
        rs1 += __shfl_xor_sync(0xffffffffu, rs1, 2);
        l0 = l0 * al0 + rs0;
        l1 = l1 * al1 + rs1;
#pragma unroll
        for (int d = 0; d < 8; d++) {
            o[d][0] *= al0; o[d][1] *= al0;
            o[d][2] *= al1; o[d][3] *= al1;
        }

        // ---- O += P V (single fp16; P in registers) ----
        const uint32_t vaddr = stg + AARR_B
            + (uint32_t)(lane & 15) * 144 + (lane >> 4) * 16;
#pragma unroll
        for (int kt = 0; kt < 4; kt++) {
            uint32_t aP[4];
            aP[0] = pack_f16(sc[2*kt][0],   sc[2*kt][1]);
            aP[1] = pack_f16(sc[2*kt][2],   sc[2*kt][3]);
            aP[2] = pack_f16(sc[2*kt+1][0], sc[2*kt+1][1]);
            aP[3] = pack_f16(sc[2*kt+1][2], sc[2*kt+1][3]);

            uint32_t bV[4][4];
#pragma unroll
            for (int dp = 0; dp < 4; dp++)
                ldsm4t(bV[dp], vaddr + kt * 2304 + dp * 32);
#pragma unroll
            for (int dp = 0; dp < 4; dp++) {
                mma_f16(o[2*dp],   aP, &bV[dp][0]);
                mma_f16(o[2*dp+1], aP, &bV[dp][2]);
            }
        }
    }

    // ---- epilogue: /l, split to bf16 hi/lo for O-projection ----
    const float inv0 = 1.0f / l0, inv1 = 1.0f / l1;
#pragma unroll
    for (int dt = 0; dt < 8; dt++) {
        size_t idx = hb + (qrow0 + w * 16 + gr) * DD + dt * 8 + gc * 2;
        uint32_t hh, ll;
        cvt_split2(o[dt][0] * inv0, o[dt][1] * inv0, hh, ll);
        *(uint32_t*)&g_Ahi[idx] = hh;
        *(uint32_t*)&g_Alo[idx] = ll;
        size_t idx8 = idx + 8 * DD;
        cvt_split2(o[dt][2] * inv1, o[dt][3] * inv1, hh, ll);
        *(uint32_t*)&g_Ahi[idx8] = hh;
        *(uint32_t*)&g_Alo[idx8] = ll;
    }
}

// ---------------------------------------------------------------------------
extern "C" void kernel_launch(void* const* d_in, const int* in_sizes, int n_in,
                              void* d_out, int out_size)
{
    (void)in_sizes; (void)n_in; (void)out_size;
    const float* x  = (const float*)d_in[0];
    const float* Wq = (const float*)d_in[1];
    const float* bq = (const float*)d_in[2];
    const float* Wk = (const float*)d_in[3];
    const float* bk = (const float*)d_in[4];
    const float* Wv = (const float*)d_in[5];
    const float* bv = (const float*)d_in[6];
    const float* Wo = (const float*)d_in[7];
    const float* bo = (const float*)d_in[8];
    float* out = (float*)d_out;

    __nv_bfloat16 *xh, *xl;
    cudaGetSymbolAddress((void**)&xh, g_xhi);
    cudaGetSymbolAddress((void**)&xl, g_xlo);

    cudaFuncSetAttribute(gemm_qkv_kernel,
                         cudaFuncAttributeMaxDynamicSharedMemorySize, GSMEM_TOTAL);
    cudaFuncSetAttribute(gemm_o_kernel,
                         cudaFuncAttributeMaxDynamicSharedMemorySize, GSMEM_TOTAL);
    cudaFuncSetAttribute(attn_mma_kernel,
                         cudaFuncAttributeMaxDynamicSharedMemorySize, ASMEM_TOTAL);

    prep_kernel<<<12544, 256>>>(x, Wq, Wk, Wv, Wo);

    gemm_qkv_kernel<<<dim3(DD / 128, MM / 128, 3), 256, GSMEM_TOTAL>>>(
        xh, xl, bq, bk, bv);

    attn_mma_kernel<<<dim3(SS / 128, HH, BB), 256, ASMEM_TOTAL>>>();

    gemm_o_kernel<<<dim3(DD / 128, MM / 128), 256, GSMEM_TOTAL>>>(bo, out);
}

// round 13
// speedup vs baseline: 1.1247x; 1.0147x over previous
#include <cuda_runtime.h>
#include <cuda_bf16.h>
#include <cuda_fp16.h>
#include <cstdint>

// Problem constants
#define BB 4
#define SS 2048
#define DD 1024
#define HH 16
#define HDIM 64
#define MM (BB * SS)   // 8192

// log2(e) * 0.125 (softmax scale folded into Q, exp2 domain)
#define QSC 0.18033688011112042f

// ---------------------------------------------------------------------------
// Device-global scratch (allocation-free rule)
// ---------------------------------------------------------------------------
__device__ __nv_bfloat16 g_xhi[(size_t)MM * DD], g_xlo[(size_t)MM * DD];
__device__ __nv_bfloat16 g_Wqh[DD * DD], g_Wql[DD * DD];
__device__ __nv_bfloat16 g_Wkh[DD * DD], g_Wkl[DD * DD];
__device__ __nv_bfloat16 g_Wvh[DD * DD], g_Wvl[DD * DD];
__device__ __nv_bfloat16 g_Woh[DD * DD], g_Wol[DD * DD];
__device__ __half g_Qh[(size_t)MM * DD];    // single fp16 (scaled)
__device__ __half g_Kh[(size_t)MM * DD];    // single fp16
__device__ __half g_Vh[(size_t)MM * DD];    // single fp16
__device__ __nv_bfloat16 g_Ahi[(size_t)MM * DD], g_Alo[(size_t)MM * DD];
__device__ float g_cos[SS * 32];
__device__ float g_sin[SS * 32];

// ---------------------------------------------------------------------------
// PTX helpers (portable sm_80+: ldmatrix, mma.sync, cp.async)
// ---------------------------------------------------------------------------
__device__ __forceinline__ uint32_t smem_u32(const void* p) {
    uint32_t a;
    asm("{ .reg .u64 t; cvta.to.shared.u64 t, %1; cvt.u32.u64 %0, t; }"
        : "=r"(a) : "l"(p));
    return a;
}

__device__ __forceinline__ void ldsm4(uint32_t* r, uint32_t addr) {
    asm volatile("ldmatrix.sync.aligned.m8n8.x4.shared.b16 {%0,%1,%2,%3}, [%4];"
        : "=r"(r[0]), "=r"(r[1]), "=r"(r[2]), "=r"(r[3]) : "r"(addr));
}

__device__ __forceinline__ void ldsm4t(uint32_t* r, uint32_t addr) {
    asm volatile("ldmatrix.sync.aligned.m8n8.x4.trans.shared.b16 {%0,%1,%2,%3}, [%4];"
        : "=r"(r[0]), "=r"(r[1]), "=r"(r[2]), "=r"(r[3]) : "r"(addr));
}

__device__ __forceinline__ void mma_bf16(float* c, const uint32_t* a, const uint32_t* b) {
    asm volatile(
        "mma.sync.aligned.m16n8k16.row.col.f32.bf16.bf16.f32 "
        "{%0,%1,%2,%3}, {%4,%5,%6,%7}, {%8,%9}, {%0,%1,%2,%3};"
        : "+f"(c[0]), "+f"(c[1]), "+f"(c[2]), "+f"(c[3])
        : "r"(a[0]), "r"(a[1]), "r"(a[2]), "r"(a[3]), "r"(b[0]), "r"(b[1]));
}

__device__ __forceinline__ void mma_f16(float* c, const uint32_t* a, const uint32_t* b) {
    asm volatile(
        "mma.sync.aligned.m16n8k16.row.col.f32.f16.f16.f32 "
        "{%0,%1,%2,%3}, {%4,%5,%6,%7}, {%8,%9}, {%0,%1,%2,%3};"
        : "+f"(c[0]), "+f"(c[1]), "+f"(c[2]), "+f"(c[3])
        : "r"(a[0]), "r"(a[1]), "r"(a[2]), "r"(a[3]), "r"(b[0]), "r"(b[1]));
}

__device__ __forceinline__ void cp16(uint32_t dst, const void* src) {
    asm volatile("cp.async.cg.shared.global [%0], [%1], 16;" :: "r"(dst), "l"(src));
}
#define CP_COMMIT() asm volatile("cp.async.commit_group;" ::: "memory")
#define CP_WAIT(n)  asm volatile("cp.async.wait_group %0;" :: "n"(n) : "memory")

// fp32 pair -> packed bf16x2 hi + bf16x2 lo (residual)
__device__ __forceinline__ void cvt_split2(float v0, float v1, uint32_t& h, uint32_t& l) {
    asm("cvt.rn.bf16x2.f32 %0, %1, %2;" : "=r"(h) : "f"(v1), "f"(v0));
    float r0 = v0 - __uint_as_float(h << 16);
    float r1 = v1 - __uint_as_float(h & 0xffff0000u);
    asm("cvt.rn.bf16x2.f32 %0, %1, %2;" : "=r"(l) : "f"(r1), "f"(r0));
}

// fp32 pair -> packed f16x2 (lo half = v0)
__device__ __forceinline__ uint32_t pack_f16(float v0, float v1) {
    uint32_t r;
    asm("cvt.rn.f16x2.f32 %0, %1, %2;" : "=r"(r) : "f"(v1), "f"(v0));
    return r;
}

// packed f16x2 exp2 (approx)
__device__ __forceinline__ uint32_t ex2_f16x2(uint32_t v) {
    asm("ex2.approx.f16x2 %0, %0;" : "+r"(v));
    return v;
}

// ---------------------------------------------------------------------------
// Fused prep: rope tables + x split + 4 weight splits, one launch.
// blocks [0,8192) = x, [8192,12288) = weights (1024 each), [12288,12544) = rope
// ---------------------------------------------------------------------------
__global__ __launch_bounds__(256) void prep_kernel(
    const float* __restrict__ x,
    const float* __restrict__ Wq, const float* __restrict__ Wk,
    const float* __restrict__ Wv, const float* __restrict__ Wo)
{
    const int bid = blockIdx.x;
    const int tid = threadIdx.x;

    if (bid < 8192) {                       // x: 2097152 float4 chunks
        int i = bid * 256 + tid;
        float4 v = ((const float4*)x)[i];
        uint32_t h01, h23, l01, l23;
        cvt_split2(v.x, v.y, h01, l01);
        cvt_split2(v.z, v.w, h23, l23);
        ((uint2*)g_xhi)[i] = make_uint2(h01, h23);
        ((uint2*)g_xlo)[i] = make_uint2(l01, l23);
    } else if (bid < 12288) {               // weights
        int wb = bid - 8192;
        int z = wb >> 10;
        const float* src = (z == 0) ? Wq : (z == 1) ? Wk : (z == 2) ? Wv : Wo;
        __nv_bfloat16* hi = (z == 0) ? g_Wqh : (z == 1) ? g_Wkh : (z == 2) ? g_Wvh : g_Woh;
        __nv_bfloat16* lo = (z == 0) ? g_Wql : (z == 1) ? g_Wkl : (z == 2) ? g_Wvl : g_Wol;
        int i = (wb & 1023) * 256 + tid;
        float4 v = ((const float4*)src)[i];
        uint32_t h01, h23, l01, l23;
        cvt_split2(v.x, v.y, h01, l01);
        cvt_split2(v.z, v.w, h23, l23);
        ((uint2*)hi)[i] = make_uint2(h01, h23);
        ((uint2*)lo)[i] = make_uint2(l01, l23);
    } else {                                // rope tables: S*32 entries
        int idx = (bid - 12288) * 256 + tid;
        int i = idx & 31;
        int s = idx >> 5;
        double inv_freq = exp((double)i * -0.28782313662425575);  // -ln(10000)/32
        double sd, cd;
        sincos((double)s * inv_freq, &sd, &cd);
        g_cos[idx] = (float)cd;
        g_sin[idx] = (float)sd;
    }
}

// ---------------------------------------------------------------------------
// GEMM core (bf16 3-term): 128x128 CTA, 8 warps (64x32), K-chunk 32,
// 2-stage cp.async pipeline, 80 KB smem => 2 CTAs/SM (128 regs cap).
// BANKED configuration (R12): do not modify. Bit-exact path.
// Stage (40960B): Ahi[128x80] | Alo | Whi | Wlo
// ---------------------------------------------------------------------------
#define GARR   10240            // 128 * 80
#define GSTAGE 40960
#define GSMEM_TOTAL (2 * GSTAGE)   // 81920

__device__ __forceinline__ void gemm_core(
    const __nv_bfloat16* const* srcs, uint32_t smb,
    int tid, int wid, int lid, float acc[4][4][4])
{
    const int warp_m = wid & 1, warp_n = wid >> 1;
    const int arow = lid & 15;
    const int ak16 = (lid & 16);
    const int brow = (lid & 7) | ((lid & 16) >> 1);
    const int bk16 = (lid & 8) * 2;
    const uint32_t aBase = smb + (uint32_t)(warp_m * 64 + arow) * 80 + ak16;
    const uint32_t bBase = smb + 2 * GARR
        + (uint32_t)(warp_n * 32 + brow) * 80 + bk16;

    auto issue = [&](int ck) {
        const uint32_t base = smb + (uint32_t)(ck & 1) * GSTAGE;
        const int k0 = ck * 32;
#pragma unroll
        for (int a = 0; a < 4; a++) {
#pragma unroll
            for (int i = 0; i < 2; i++) {
                int idx = tid + i * 256;        // 512 chunks per array
                int row = idx >> 2, q = idx & 3;
                cp16(base + a * GARR + row * 80 + q * 16,
                     srcs[a] + (size_t)row * DD + k0 + q * 8);
            }
        }
    };

    issue(0); CP_COMMIT();
    issue(1); CP_COMMIT();

    const int nchunks = DD / 32;   // 32
    for (int ck = 0; ck < nchunks; ck++) {
        CP_WAIT(1);
        __syncthreads();

        const uint32_t bo = (uint32_t)(ck & 1) * GSTAGE;
#pragma unroll
        for (int kk = 0; kk < 2; kk++) {
            uint32_t af[4][4], bf[2][4], bf2[2][4];
            const uint32_t ka = aBase + bo + kk * 32;
            const uint32_t kb = bBase + bo + kk * 32;
            // hi operands
#pragma unroll
            for (int mt = 0; mt < 4; mt++) ldsm4(af[mt], ka + mt * 1280);
#pragma unroll
            for (int p = 0; p < 2; p++)  ldsm4(bf[p], kb + p * 1280);
            // term hi*hi
#pragma unroll
            for (int mt = 0; mt < 4; mt++)
#pragma unroll
                for (int nt = 0; nt < 4; nt++)
                    mma_bf16(acc[mt][nt], af[mt], &bf[nt >> 1][(nt & 1) * 2]);
            // term hi*lo
#pragma unroll
            for (int p = 0; p < 2; p++)  ldsm4(bf2[p], kb + GARR + p * 1280);
#pragma unroll
            for (int mt = 0; mt < 4; mt++)
#pragma unroll
                for (int nt = 0; nt < 4; nt++)
                    mma_bf16(acc[mt][nt], af[mt], &bf2[nt >> 1][(nt & 1) * 2]);
            // term lo*hi (af overwritten with Alo)
#pragma unroll
            for (int mt = 0; mt < 4; mt++) ldsm4(af[mt], ka + GARR + mt * 1280);
#pragma unroll
            for (int mt = 0; mt < 4; mt++)
#pragma unroll
                for (int nt = 0; nt < 4; nt++)
                    mma_bf16(acc[mt][nt], af[mt], &bf[nt >> 1][(nt & 1) * 2]);
        }
        __syncthreads();
        if (ck + 2 < nchunks) issue(ck + 2);
        CP_COMMIT();
    }
}

// ---------------------------------------------------------------------------
// Fused QKV GEMM: z = 0:Q, 1:K, 2:V.  Epilogue fuses RoPE + fp16 store.
// ---------------------------------------------------------------------------
__global__ __launch_bounds__(256, 2) void gemm_qkv_kernel(
    const __nv_bfloat16* __restrict__ xh, const __nv_bfloat16* __restrict__ xl,
    const float* __restrict__ bq, const float* __restrict__ bk,
    const float* __restrict__ bv)
{
    extern __shared__ char sm[];
    const uint32_t smb = smem_u32(sm);
    const int tid = threadIdx.x;
    const int wid = tid >> 5, lid = tid & 31;
    const int bm = blockIdx.y * 128, bn = blockIdx.x * 128;
    const int z = blockIdx.z;
    const int warp_m = wid & 1, warp_n = wid >> 1;

    const __nv_bfloat16* Whi = (z == 0) ? g_Wqh : (z == 1) ? g_Wkh : g_Wvh;
    const __nv_bfloat16* Wlo = (z == 0) ? g_Wql : (z == 1) ? g_Wkl : g_Wvl;
    const float* bias = (z == 0) ? bq : (z == 1) ? bk : bv;

    const __nv_bfloat16* srcs[4] = {
        xh + (size_t)bm * DD, xl + (size_t)bm * DD,
        Whi + (size_t)bn * DD, Wlo + (size_t)bn * DD };

    float acc[4][4][4];
#pragma unroll
    for (int i = 0; i < 4; i++)
#pragma unroll
        for (int j = 0; j < 4; j++)
#pragma unroll
            for (int v = 0; v < 4; v++) acc[i][j][v] = 0.f;

    gemm_core(srcs, smb, tid, wid, lid, acc);

    const int gr = lid >> 2, gc = lid & 3;

    if (z == 2) {
        // V: direct single-fp16 store (+bias)
#pragma unroll
        for (int nt = 0; nt < 4; nt++) {
            const int col = bn + warp_n * 32 + nt * 8 + gc * 2;
            const float2 bv2 = *(const float2*)(bias + col);
#pragma unroll
            for (int mt = 0; mt < 4; mt++) {
                const int row = bm + warp_m * 64 + mt * 16 + gr;
                *(uint32_t*)&g_Vh[(size_t)row * DD + col] =
                    pack_f16(acc[mt][nt][0] + bv2.x, acc[mt][nt][1] + bv2.y);
                *(uint32_t*)&g_Vh[(size_t)(row + 8) * DD + col] =
                    pack_f16(acc[mt][nt][2] + bv2.x, acc[mt][nt][3] + bv2.y);
            }
        }
        return;
    }

    // Q/K: stage to smem (+bias), then RoPE across (i, i+32) pairs.
    CP_WAIT(0);
    __syncthreads();
    float* Ds = (float*)sm;    // [128][132] = 67584 B < 81920
#pragma unroll
    for (int nt = 0; nt < 4; nt++) {
        const int cl = warp_n * 32 + nt * 8 + gc * 2;
        const float2 bv2 = *(const float2*)(bias + bn + cl);
#pragma unroll
        for (int mt = 0; mt < 4; mt++) {
            const int rl = warp_m * 64 + mt * 16 + gr;
            Ds[rl * 132 + cl]     = acc[mt][nt][0] + bv2.x;
            Ds[rl * 132 + cl + 1] = acc[mt][nt][1] + bv2.y;
            Ds[(rl + 8) * 132 + cl]     = acc[mt][nt][2] + bv2.x;
            Ds[(rl + 8) * 132 + cl + 1] = acc[mt][nt][3] + bv2.y;
        }
    }
    __syncthreads();

    for (int u = tid; u < 128 * 32; u += 256) {
        const int row = u >> 5, t = u & 31;
        const int hl = t >> 4, tt = t & 15;
        const int col = hl * 64 + tt * 2;
        const int s = (bm + row) & (SS - 1);
        const int i0 = tt * 2;
        const float cs0 = g_cos[s * 32 + i0], sn0 = g_sin[s * 32 + i0];
        const float cs1 = g_cos[s * 32 + i0 + 1], sn1 = g_sin[s * 32 + i0 + 1];
        const float v1a = Ds[row * 132 + col],      v1b = Ds[row * 132 + col + 1];
        const float v2a = Ds[row * 132 + col + 32], v2b = Ds[row * 132 + col + 33];
        const float r1a = v1a * cs0 - v2a * sn0, r2a = v2a * cs0 + v1a * sn0;
        const float r1b = v1b * cs1 - v2b * sn1, r2b = v2b * cs1 + v1b * sn1;
        const size_t out = (size_t)(bm + row) * DD + bn + col;
        if (z == 0) {
            *(uint32_t*)&g_Qh[out]      = pack_f16(r1a * QSC, r1b * QSC);
            *(uint32_t*)&g_Qh[out + 32] = pack_f16(r2a * QSC, r2b * QSC);
        } else {
            *(uint32_t*)&g_Kh[out]      = pack_f16(r1a, r1b);
            *(uint32_t*)&g_Kh[out + 32] = pack_f16(r2a, r2b);
        }
    }
}

// ---------------------------------------------------------------------------
// O-projection GEMM: out = A @ Wo^T + bo, fp32 out.
// ---------------------------------------------------------------------------
__global__ __launch_bounds__(256, 2) void gemm_o_kernel(
    const float* __restrict__ bias, float* __restrict__ C)
{
    extern __shared__ char sm[];
    const uint32_t smb = smem_u32(sm);
    const int tid = threadIdx.x;
    const int wid = tid >> 5, lid = tid & 31;
    const int bm = blockIdx.y * 128, bn = blockIdx.x * 128;
    const int warp_m = wid & 1, warp_n = wid >> 1;

    const __nv_bfloat16* srcs[4] = {
        g_Ahi + (size_t)bm * DD, g_Alo + (size_t)bm * DD,
        g_Woh + (size_t)bn * DD, g_Wol + (size_t)bn * DD };

    float acc[4][4][4];
#pragma unroll
    for (int i = 0; i < 4; i++)
#pragma unroll
        for (int j = 0; j < 4; j++)
#pragma unroll
            for (int v = 0; v < 4; v++) acc[i][j][v] = 0.f;

    gemm_core(srcs, smb, tid, wid, lid, acc);

    const int gr = lid >> 2, gc = lid & 3;
#pragma unroll
    for (int nt = 0; nt < 4; nt++) {
        const int col = bn + warp_n * 32 + nt * 8 + gc * 2;
        const float2 bv = *(const float2*)(bias + col);
#pragma unroll
        for (int mt = 0; mt < 4; mt++) {
            const int row = bm + warp_m * 64 + mt * 16 + gr;
            *(float2*)(C + (size_t)row * DD + col) =
                make_float2(acc[mt][nt][0] + bv.x, acc[mt][nt][1] + bv.y);
            *(float2*)(C + (size_t)(row + 8) * DD + col) =
                make_float2(acc[mt][nt][2] + bv.x, acc[mt][nt][3] + bv.y);
        }
    }
}

// ---------------------------------------------------------------------------
// HMMA causal flash attention, all-single-fp16 operands. 2 CTAs/SM.
// BR=128 (8 warps x 16 rows), BC=64. 64 MMAs/tile/warp. 4-deep cp.async.
// NEW: packed ex2.approx.f16x2 for P (MUFU halved, P pre-packed) and row
// sums via ones-MMA (exact fp32, no shuffles, no fadd tree).
// ---------------------------------------------------------------------------
#define AQ_B   18432            // 128*144
#define AARR_B 9216             // 64*144
#define ASTG_B (2 * AARR_B)     // 18432
#define ASMEM_TOTAL (AQ_B + 4 * ASTG_B)   // 92160

__global__ __launch_bounds__(256, 2) void attn_mma_kernel()
{
    extern __shared__ char sm[];
    const uint32_t smb = smem_u32(sm);
    const int tid = threadIdx.x;
    const int w = tid >> 5, lane = tid & 31;
    const int gr = lane >> 2, gc = lane & 3;
    const int qt = (int)gridDim.x - 1 - (int)blockIdx.x;   // long blocks first
    const int h = blockIdx.y, b = blockIdx.z;

    const size_t hb = ((size_t)b * SS) * DD + (size_t)h * HDIM;
    const size_t qrow0 = (size_t)qt * 128;

    const int ntiles = 2 * qt + 2;

    // --- prologue: Q tile (single fp16) ---
#pragma unroll
    for (int i = 0; i < 4; i++) {
        int idx = tid + i * 256;          // 1024 chunks
        int row = idx >> 3, c = idx & 7;
        cp16(smb + row * 144 + c * 16, g_Qh + hb + (qrow0 + row) * DD + c * 8);
    }
    CP_COMMIT();

    auto stage_load = [&](int jt, int s) {
        const uint32_t base = smb + AQ_B + (uint32_t)s * ASTG_B;
#pragma unroll
        for (int i = 0; i < 2; i++) {
            int idx = tid + i * 256;       // 512 chunks per array
            int row = idx >> 3, c = idx & 7;
            cp16(base + row * 144 + c * 16,
                 g_Kh + hb + (size_t)(jt * 64 + row) * DD + c * 8);
            cp16(base + AARR_B + row * 144 + c * 16,
                 g_Vh + hb + (size_t)(jt * 64 + row) * DD + c * 8);
        }
    };
    stage_load(0, 0); CP_COMMIT();
    if (1 < ntiles) stage_load(1, 1);
    CP_COMMIT();
    if (2 < ntiles) stage_load(2, 2);
    CP_COMMIT();

    float m0 = -1e30f, m1 = -1e30f, l0 = 0.f, l1 = 0.f;
    float o[8][4];
#pragma unroll
    for (int d = 0; d < 8; d++)
#pragma unroll
        for (int v = 0; v < 4; v++) o[d][v] = 0.f;

    uint32_t aQ[4][4];
    const int qrow_lo = qt * 128 + w * 16 + gr;

    for (int jt = 0; jt < ntiles; jt++) {
        CP_WAIT(2);
        __syncthreads();
        if (jt + 3 < ntiles) stage_load(jt + 3, (jt + 3) & 3);
        CP_COMMIT();

        if (jt == 0) {   // Q fragments (loop-invariant; Q group completed)
            const uint32_t qa = smb + (uint32_t)(w * 16 + (lane & 15)) * 144
                                + (lane >> 4) * 16;
#pragma unroll
            for (int kt = 0; kt < 4; kt++) ldsm4(aQ[kt], qa + kt * 32);
        }

        const uint32_t stg = smb + AQ_B + (uint32_t)(jt & 3) * ASTG_B;

        // ---- S = Q K^T (single fp16) ----
        float sc[8][4];
#pragma unroll
        for (int nt = 0; nt < 8; nt++)
#pragma unroll
            for (int v = 0; v < 4; v++) sc[nt][v] = 0.f;

        const uint32_t kaddr = stg
            + (uint32_t)((lane & 7) | ((lane & 16) >> 1)) * 144 + (lane & 8) * 2;
#pragma unroll
        for (int kt = 0; kt < 4; kt++) {
            uint32_t bK[4][4];
#pragma unroll
            for (int np = 0; np < 4; np++)
                ldsm4(bK[np], kaddr + np * 2304 + kt * 32);
#pragma unroll
            for (int np = 0; np < 4; np++) {
                mma_f16(sc[2*np],   aQ[kt], &bK[np][0]);
                mma_f16(sc[2*np+1], aQ[kt], &bK[np][2]);
            }
        }

        // ---- causal mask (only last two tiles) ----
        if (jt >= 2 * qt) {
#pragma unroll
            for (int nt = 0; nt < 8; nt++) {
                int j = jt * 64 + nt * 8 + gc * 2;
                if (j     > qrow_lo)     sc[nt][0] = -1e30f;
                if (j + 1 > qrow_lo)     sc[nt][1] = -1e30f;
                if (j     > qrow_lo + 8) sc[nt][2] = -1e30f;
                if (j + 1 > qrow_lo + 8) sc[nt][3] = -1e30f;
            }
        }

        // ---- online softmax (exp2 domain) ----
        float mx0 = -1e30f, mx1 = -1e30f;
#pragma unroll
        for (int nt = 0; nt < 8; nt++) {
            mx0 = fmaxf(mx0, fmaxf(sc[nt][0], sc[nt][1]));
            mx1 = fmaxf(mx1, fmaxf(sc[nt][2], sc[nt][3]));
        }
        mx0 = fmaxf(mx0, __shfl_xor_sync(0xffffffffu, mx0, 1));
        mx0 = fmaxf(mx0, __shfl_xor_sync(0xffffffffu, mx0, 2));
        mx1 = fmaxf(mx1, __shfl_xor_sync(0xffffffffu, mx1, 1));
        mx1 = fmaxf(mx1, __shfl_xor_sync(0xffffffffu, mx1, 2));

        float mn0 = fmaxf(m0, mx0), mn1 = fmaxf(m1, mx1);
        float al0 = exp2f(m0 - mn0), al1 = exp2f(m1 - mn1);
        m0 = mn0; m1 = mn1;

        // ---- P = exp2(S - m) computed packed in fp16x2 ----
        uint32_t hP[8][2];
#pragma unroll
        for (int nt = 0; nt < 8; nt++) {
            hP[nt][0] = ex2_f16x2(pack_f16(sc[nt][0] - mn0, sc[nt][1] - mn0));
            hP[nt][1] = ex2_f16x2(pack_f16(sc[nt][2] - mn1, sc[nt][3] - mn1));
        }

        // ---- row sums via ones-MMA: exact fp32, no shuffles ----
        float lacc[4] = {0.f, 0.f, 0.f, 0.f};
        {
            const uint32_t bOnes[2] = {0x3C003C00u, 0x3C003C00u};
#pragma unroll
            for (int kt = 0; kt < 4; kt++) {
                uint32_t aP[4] = {hP[2*kt][0], hP[2*kt][1],
                                  hP[2*kt+1][0], hP[2*kt+1][1]};
                mma_f16(lacc, aP, bOnes);
            }
        }
        l0 = l0 * al0 + lacc[0];
        l1 = l1 * al1 + lacc[2];
#pragma unroll
        for (int d = 0; d < 8; d++) {
            o[d][0] *= al0; o[d][1] *= al0;
            o[d][2] *= al1; o[d][3] *= al1;
        }

        // ---- O += P V (P already packed fp16) ----
        const uint32_t vaddr = stg + AARR_B
            + (uint32_t)(lane & 15) * 144 + (lane >> 4) * 16;
#pragma unroll
        for (int kt = 0; kt < 4; kt++) {
            uint32_t aP[4] = {hP[2*kt][0], hP[2*kt][1],
                              hP[2*kt+1][0], hP[2*kt+1][1]};

            uint32_t bV[4][4];
#pragma unroll
            for (int dp = 0; dp < 4; dp++)
                ldsm4t(bV[dp], vaddr + kt * 2304 + dp * 32);
#pragma unroll
            for (int dp = 0; dp < 4; dp++) {
                mma_f16(o[2*dp],   aP, &bV[dp][0]);
                mma_f16(o[2*dp+1], aP, &bV[dp][2]);
            }
        }
    }

    // ---- epilogue: /l, split to bf16 hi/lo for O-projection ----
    const float inv0 = 1.0f / l0, inv1 = 1.0f / l1;
#pragma unroll
    for (int dt = 0; dt < 8; dt++) {
        size_t idx = hb + (qrow0 + w * 16 + gr) * DD + dt * 8 + gc * 2;
        uint32_t hh, ll;
        cvt_split2(o[dt][0] * inv0, o[dt][1] * inv0, hh, ll);
        *(uint32_t*)&g_Ahi[idx] = hh;
        *(uint32_t*)&g_Alo[idx] = ll;
        size_t idx8 = idx + 8 * DD;
        cvt_split2(o[dt][2] * inv1, o[dt][3] * inv1, hh, ll);
        *(uint32_t*)&g_Ahi[idx8] = hh;
        *(uint32_t*)&g_Alo[idx8] = ll;
    }
}

// ---------------------------------------------------------------------------
extern "C" void kernel_launch(void* const* d_in, const int* in_sizes, int n_in,
                              void* d_out, int out_size)
{
    (void)in_sizes; (void)n_in; (void)out_size;
    const float* x  = (const float*)d_in[0];
    const float* Wq = (const float*)d_in[1];
    const float* bq = (const float*)d_in[2];
    const float* Wk = (const float*)d_in[3];
    const float* bk = (const float*)d_in[4];
    const float* Wv = (const float*)d_in[5];
    const float* bv = (const float*)d_in[6];
    const float* Wo = (const float*)d_in[7];
    const float* bo = (const float*)d_in[8];
    float* out = (float*)d_out;

    __nv_bfloat16 *xh, *xl;
    cudaGetSymbolAddress((void**)&xh, g_xhi);
    cudaGetSymbolAddress((void**)&xl, g_xlo);

    cudaFuncSetAttribute(gemm_qkv_kernel,
                         cudaFuncAttributeMaxDynamicSharedMemorySize, GSMEM_TOTAL);
    cudaFuncSetAttribute(gemm_o_kernel,
                         cudaFuncAttributeMaxDynamicSharedMemorySize, GSMEM_TOTAL);
    cudaFuncSetAttribute(attn_mma_kernel,
                         cudaFuncAttributeMaxDynamicSharedMemorySize, ASMEM_TOTAL);

    prep_kernel<<<12544, 256>>>(x, Wq, Wk, Wv, Wo);

    gemm_qkv_kernel<<<dim3(DD / 128, MM / 128, 3), 256, GSMEM_TOTAL>>>(
        xh, xl, bq, bk, bv);

    attn_mma_kernel<<<dim3(SS / 128, HH, BB), 256, ASMEM_TOTAL>>>();

    gemm_o_kernel<<<dim3(DD / 128, MM / 128), 256, GSMEM_TOTAL>>>(bo, out);
}

// round 14
// speedup vs baseline: 1.1264x; 1.0015x over previous
#include <cuda_runtime.h>
#include <cuda_bf16.h>
#include <cuda_fp16.h>
#include <cstdint>

// Problem constants
#define BB 4
#define SS 2048
#define DD 1024
#define HH 16
#define HDIM 64
#define MM (BB * SS)   // 8192

// log2(e) * 0.125 (softmax scale folded into Q, exp2 domain)
#define QSC 0.18033688011112042f

// ---------------------------------------------------------------------------
// Device-global scratch (allocation-free rule)
// ---------------------------------------------------------------------------
__device__ __nv_bfloat16 g_xhi[(size_t)MM * DD], g_xlo[(size_t)MM * DD];
__device__ __nv_bfloat16 g_Wqh[DD * DD], g_Wql[DD * DD];
__device__ __nv_bfloat16 g_Wkh[DD * DD], g_Wkl[DD * DD];
__device__ __nv_bfloat16 g_Wvh[DD * DD], g_Wvl[DD * DD];
__device__ __nv_bfloat16 g_Woh[DD * DD], g_Wol[DD * DD];
__device__ __half g_Qh[(size_t)MM * DD];    // single fp16 (scaled)
__device__ __half g_Kh[(size_t)MM * DD];    // single fp16
__device__ __half g_Vh[(size_t)MM * DD];    // single fp16
__device__ __nv_bfloat16 g_Ahi[(size_t)MM * DD], g_Alo[(size_t)MM * DD];
__device__ float g_cos[SS * 32];
__device__ float g_sin[SS * 32];

// ---------------------------------------------------------------------------
// PTX helpers (portable sm_80+: ldmatrix, mma.sync, cp.async)
// ---------------------------------------------------------------------------
__device__ __forceinline__ uint32_t smem_u32(const void* p) {
    uint32_t a;
    asm("{ .reg .u64 t; cvta.to.shared.u64 t, %1; cvt.u32.u64 %0, t; }"
        : "=r"(a) : "l"(p));
    return a;
}

__device__ __forceinline__ void ldsm4(uint32_t* r, uint32_t addr) {
    asm volatile("ldmatrix.sync.aligned.m8n8.x4.shared.b16 {%0,%1,%2,%3}, [%4];"
        : "=r"(r[0]), "=r"(r[1]), "=r"(r[2]), "=r"(r[3]) : "r"(addr));
}

__device__ __forceinline__ void ldsm4t(uint32_t* r, uint32_t addr) {
    asm volatile("ldmatrix.sync.aligned.m8n8.x4.trans.shared.b16 {%0,%1,%2,%3}, [%4];"
        : "=r"(r[0]), "=r"(r[1]), "=r"(r[2]), "=r"(r[3]) : "r"(addr));
}

__device__ __forceinline__ void mma_bf16(float* c, const uint32_t* a, const uint32_t* b) {
    asm volatile(
        "mma.sync.aligned.m16n8k16.row.col.f32.bf16.bf16.f32 "
        "{%0,%1,%2,%3}, {%4,%5,%6,%7}, {%8,%9}, {%0,%1,%2,%3};"
        : "+f"(c[0]), "+f"(c[1]), "+f"(c[2]), "+f"(c[3])
        : "r"(a[0]), "r"(a[1]), "r"(a[2]), "r"(a[3]), "r"(b[0]), "r"(b[1]));
}

__device__ __forceinline__ void mma_f16(float* c, const uint32_t* a, const uint32_t* b) {
    asm volatile(
        "mma.sync.aligned.m16n8k16.row.col.f32.f16.f16.f32 "
        "{%0,%1,%2,%3}, {%4,%5,%6,%7}, {%8,%9}, {%0,%1,%2,%3};"
        : "+f"(c[0]), "+f"(c[1]), "+f"(c[2]), "+f"(c[3])
        : "r"(a[0]), "r"(a[1]), "r"(a[2]), "r"(a[3]), "r"(b[0]), "r"(b[1]));
}

__device__ __forceinline__ void cp16(uint32_t dst, const void* src) {
    asm volatile("cp.async.cg.shared.global [%0], [%1], 16;" :: "r"(dst), "l"(src));
}
#define CP_COMMIT() asm volatile("cp.async.commit_group;" ::: "memory")
#define CP_WAIT(n)  asm volatile("cp.async.wait_group %0;" :: "n"(n) : "memory")

// fp32 pair -> packed bf16x2 hi + bf16x2 lo (residual)
__device__ __forceinline__ void cvt_split2(float v0, float v1, uint32_t& h, uint32_t& l) {
    asm("cvt.rn.bf16x2.f32 %0, %1, %2;" : "=r"(h) : "f"(v1), "f"(v0));
    float r0 = v0 - __uint_as_float(h << 16);
    float r1 = v1 - __uint_as_float(h & 0xffff0000u);
    asm("cvt.rn.bf16x2.f32 %0, %1, %2;" : "=r"(l) : "f"(r1), "f"(r0));
}

// fp32 pair -> packed f16x2 (lo half = v0)
__device__ __forceinline__ uint32_t pack_f16(float v0, float v1) {
    uint32_t r;
    asm("cvt.rn.f16x2.f32 %0, %1, %2;" : "=r"(r) : "f"(v1), "f"(v0));
    return r;
}

// packed f16x2 exp2 (approx)
__device__ __forceinline__ uint32_t ex2_f16x2(uint32_t v) {
    asm("ex2.approx.f16x2 %0, %0;" : "+r"(v));
    return v;
}

// ---------------------------------------------------------------------------
// Fused prep: rope tables + x split + 4 weight splits, one launch.
// blocks [0,8192) = x, [8192,12288) = weights (1024 each), [12288,12544) = rope
// ---------------------------------------------------------------------------
__global__ __launch_bounds__(256) void prep_kernel(
    const float* __restrict__ x,
    const float* __restrict__ Wq, const float* __restrict__ Wk,
    const float* __restrict__ Wv, const float* __restrict__ Wo)
{
    const int bid = blockIdx.x;
    const int tid = threadIdx.x;

    if (bid < 8192) {                       // x: 2097152 float4 chunks
        int i = bid * 256 + tid;
        float4 v = ((const float4*)x)[i];
        uint32_t h01, h23, l01, l23;
        cvt_split2(v.x, v.y, h01, l01);
        cvt_split2(v.z, v.w, h23, l23);
        ((uint2*)g_xhi)[i] = make_uint2(h01, h23);
        ((uint2*)g_xlo)[i] = make_uint2(l01, l23);
    } else if (bid < 12288) {               // weights
        int wb = bid - 8192;
        int z = wb >> 10;
        const float* src = (z == 0) ? Wq : (z == 1) ? Wk : (z == 2) ? Wv : Wo;
        __nv_bfloat16* hi = (z == 0) ? g_Wqh : (z == 1) ? g_Wkh : (z == 2) ? g_Wvh : g_Woh;
        __nv_bfloat16* lo = (z == 0) ? g_Wql : (z == 1) ? g_Wkl : (z == 2) ? g_Wvl : g_Wol;
        int i = (wb & 1023) * 256 + tid;
        float4 v = ((const float4*)src)[i];
        uint32_t h01, h23, l01, l23;
        cvt_split2(v.x, v.y, h01, l01);
        cvt_split2(v.z, v.w, h23, l23);
        ((uint2*)hi)[i] = make_uint2(h01, h23);
        ((uint2*)lo)[i] = make_uint2(l01, l23);
    } else {                                // rope tables: S*32 entries
        int idx = (bid - 12288) * 256 + tid;
        int i = idx & 31;
        int s = idx >> 5;
        double inv_freq = exp((double)i * -0.28782313662425575);  // -ln(10000)/32
        double sd, cd;
        sincos((double)s * inv_freq, &sd, &cd);
        g_cos[idx] = (float)cd;
        g_sin[idx] = (float)sd;
    }
}

// ---------------------------------------------------------------------------
// GEMM core (bf16 3-term): 128x128 CTA, 8 warps (64x32), K-chunk 32,
// 2-stage cp.async pipeline, 80 KB smem => 2 CTAs/SM (128 regs cap).
// BANKED configuration (R12): do not modify. Bit-exact path.
// Stage (40960B): Ahi[128x80] | Alo | Whi | Wlo
// ---------------------------------------------------------------------------
#define GARR   10240            // 128 * 80
#define GSTAGE 40960
#define GSMEM_TOTAL (2 * GSTAGE)   // 81920

__device__ __forceinline__ void gemm_core(
    const __nv_bfloat16* const* srcs, uint32_t smb,
    int tid, int wid, int lid, float acc[4][4][4])
{
    const int warp_m = wid & 1, warp_n = wid >> 1;
    const int arow = lid & 15;
    const int ak16 = (lid & 16);
    const int brow = (lid & 7) | ((lid & 16) >> 1);
    const int bk16 = (lid & 8) * 2;
    const uint32_t aBase = smb + (uint32_t)(warp_m * 64 + arow) * 80 + ak16;
    const uint32_t bBase = smb + 2 * GARR
        + (uint32_t)(warp_n * 32 + brow) * 80 + bk16;

    auto issue = [&](int ck) {
        const uint32_t base = smb + (uint32_t)(ck & 1) * GSTAGE;
        const int k0 = ck * 32;
#pragma unroll
        for (int a = 0; a < 4; a++) {
#pragma unroll
            for (int i = 0; i < 2; i++) {
                int idx = tid + i * 256;        // 512 chunks per array
                int row = idx >> 2, q = idx & 3;
                cp16(base + a * GARR + row * 80 + q * 16,
                     srcs[a] + (size_t)row * DD + k0 + q * 8);
            }
        }
    };

    issue(0); CP_COMMIT();
    issue(1); CP_COMMIT();

    const int nchunks = DD / 32;   // 32
    for (int ck = 0; ck < nchunks; ck++) {
        CP_WAIT(1);
        __syncthreads();

        const uint32_t bo = (uint32_t)(ck & 1) * GSTAGE;
#pragma unroll
        for (int kk = 0; kk < 2; kk++) {
            uint32_t af[4][4], bf[2][4], bf2[2][4];
            const uint32_t ka = aBase + bo + kk * 32;
            const uint32_t kb = bBase + bo + kk * 32;
            // hi operands
#pragma unroll
            for (int mt = 0; mt < 4; mt++) ldsm4(af[mt], ka + mt * 1280);
#pragma unroll
            for (int p = 0; p < 2; p++)  ldsm4(bf[p], kb + p * 1280);
            // term hi*hi
#pragma unroll
            for (int mt = 0; mt < 4; mt++)
#pragma unroll
                for (int nt = 0; nt < 4; nt++)
                    mma_bf16(acc[mt][nt], af[mt], &bf[nt >> 1][(nt & 1) * 2]);
            // term hi*lo
#pragma unroll
            for (int p = 0; p < 2; p++)  ldsm4(bf2[p], kb + GARR + p * 1280);
#pragma unroll
            for (int mt = 0; mt < 4; mt++)
#pragma unroll
                for (int nt = 0; nt < 4; nt++)
                    mma_bf16(acc[mt][nt], af[mt], &bf2[nt >> 1][(nt & 1) * 2]);
            // term lo*hi (af overwritten with Alo)
#pragma unroll
            for (int mt = 0; mt < 4; mt++) ldsm4(af[mt], ka + GARR + mt * 1280);
#pragma unroll
            for (int mt = 0; mt < 4; mt++)
#pragma unroll
                for (int nt = 0; nt < 4; nt++)
                    mma_bf16(acc[mt][nt], af[mt], &bf[nt >> 1][(nt & 1) * 2]);
        }
        __syncthreads();
        if (ck + 2 < nchunks) issue(ck + 2);
        CP_COMMIT();
    }
}

// ---------------------------------------------------------------------------
// Fused QKV GEMM: z = 0:Q, 1:K, 2:V.  Epilogue fuses RoPE + fp16 store.
// ---------------------------------------------------------------------------
__global__ __launch_bounds__(256, 2) void gemm_qkv_kernel(
    const __nv_bfloat16* __restrict__ xh, const __nv_bfloat16* __restrict__ xl,
    const float* __restrict__ bq, const float* __restrict__ bk,
    const float* __restrict__ bv)
{
    extern __shared__ char sm[];
    const uint32_t smb = smem_u32(sm);
    const int tid = threadIdx.x;
    const int wid = tid >> 5, lid = tid & 31;
    const int bm = blockIdx.y * 128, bn = blockIdx.x * 128;
    const int z = blockIdx.z;
    const int warp_m = wid & 1, warp_n = wid >> 1;

    const __nv_bfloat16* Whi = (z == 0) ? g_Wqh : (z == 1) ? g_Wkh : g_Wvh;
    const __nv_bfloat16* Wlo = (z == 0) ? g_Wql : (z == 1) ? g_Wkl : g_Wvl;
    const float* bias = (z == 0) ? bq : (z == 1) ? bk : bv;

    const __nv_bfloat16* srcs[4] = {
        xh + (size_t)bm * DD, xl + (size_t)bm * DD,
        Whi + (size_t)bn * DD, Wlo + (size_t)bn * DD };

    float acc[4][4][4];
#pragma unroll
    for (int i = 0; i < 4; i++)
#pragma unroll
        for (int j = 0; j < 4; j++)
#pragma unroll
            for (int v = 0; v < 4; v++) acc[i][j][v] = 0.f;

    gemm_core(srcs, smb, tid, wid, lid, acc);

    const int gr = lid >> 2, gc = lid & 3;

    if (z == 2) {
        // V: direct single-fp16 store (+bias)
#pragma unroll
        for (int nt = 0; nt < 4; nt++) {
            const int col = bn + warp_n * 32 + nt * 8 + gc * 2;
            const float2 bv2 = *(const float2*)(bias + col);
#pragma unroll
            for (int mt = 0; mt < 4; mt++) {
                const int row = bm + warp_m * 64 + mt * 16 + gr;
                *(uint32_t*)&g_Vh[(size_t)row * DD + col] =
                    pack_f16(acc[mt][nt][0] + bv2.x, acc[mt][nt][1] + bv2.y);
                *(uint32_t*)&g_Vh[(size_t)(row + 8) * DD + col] =
                    pack_f16(acc[mt][nt][2] + bv2.x, acc[mt][nt][3] + bv2.y);
            }
        }
        return;
    }

    // Q/K: stage to smem (+bias), then RoPE across (i, i+32) pairs.
    CP_WAIT(0);
    __syncthreads();
    float* Ds = (float*)sm;    // [128][132] = 67584 B < 81920
#pragma unroll
    for (int nt = 0; nt < 4; nt++) {
        const int cl = warp_n * 32 + nt * 8 + gc * 2;
        const float2 bv2 = *(const float2*)(bias + bn + cl);
#pragma unroll
        for (int mt = 0; mt < 4; mt++) {
            const int rl = warp_m * 64 + mt * 16 + gr;
            Ds[rl * 132 + cl]     = acc[mt][nt][0] + bv2.x;
            Ds[rl * 132 + cl + 1] = acc[mt][nt][1] + bv2.y;
            Ds[(rl + 8) * 132 + cl]     = acc[mt][nt][2] + bv2.x;
            Ds[(rl + 8) * 132 + cl + 1] = acc[mt][nt][3] + bv2.y;
        }
    }
    __syncthreads();

    for (int u = tid; u < 128 * 32; u += 256) {
        const int row = u >> 5, t = u & 31;
        const int hl = t >> 4, tt = t & 15;
        const int col = hl * 64 + tt * 2;
        const int s = (bm + row) & (SS - 1);
        const int i0 = tt * 2;
        const float cs0 = g_cos[s * 32 + i0], sn0 = g_sin[s * 32 + i0];
        const float cs1 = g_cos[s * 32 + i0 + 1], sn1 = g_sin[s * 32 + i0 + 1];
        const float v1a = Ds[row * 132 + col],      v1b = Ds[row * 132 + col + 1];
        const float v2a = Ds[row * 132 + col + 32], v2b = Ds[row * 132 + col + 33];
        const float r1a = v1a * cs0 - v2a * sn0, r2a = v2a * cs0 + v1a * sn0;
        const float r1b = v1b * cs1 - v2b * sn1, r2b = v2b * cs1 + v1b * sn1;
        const size_t out = (size_t)(bm + row) * DD + bn + col;
        if (z == 0) {
            *(uint32_t*)&g_Qh[out]      = pack_f16(r1a * QSC, r1b * QSC);
            *(uint32_t*)&g_Qh[out + 32] = pack_f16(r2a * QSC, r2b * QSC);
        } else {
            *(uint32_t*)&g_Kh[out]      = pack_f16(r1a, r1b);
            *(uint32_t*)&g_Kh[out + 32] = pack_f16(r2a, r2b);
        }
    }
}

// ---------------------------------------------------------------------------
// O-projection GEMM: out = A @ Wo^T + bo, fp32 out.
// ---------------------------------------------------------------------------
__global__ __launch_bounds__(256, 2) void gemm_o_kernel(
    const float* __restrict__ bias, float* __restrict__ C)
{
    extern __shared__ char sm[];
    const uint32_t smb = smem_u32(sm);
    const int tid = threadIdx.x;
    const int wid = tid >> 5, lid = tid & 31;
    const int bm = blockIdx.y * 128, bn = blockIdx.x * 128;
    const int warp_m = wid & 1, warp_n = wid >> 1;

    const __nv_bfloat16* srcs[4] = {
        g_Ahi + (size_t)bm * DD, g_Alo + (size_t)bm * DD,
        g_Woh + (size_t)bn * DD, g_Wol + (size_t)bn * DD };

    float acc[4][4][4];
#pragma unroll
    for (int i = 0; i < 4; i++)
#pragma unroll
        for (int j = 0; j < 4; j++)
#pragma unroll
            for (int v = 0; v < 4; v++) acc[i][j][v] = 0.f;

    gemm_core(srcs, smb, tid, wid, lid, acc);

    const int gr = lid >> 2, gc = lid & 3;
#pragma unroll
    for (int nt = 0; nt < 4; nt++) {
        const int col = bn + warp_n * 32 + nt * 8 + gc * 2;
        const float2 bv = *(const float2*)(bias + col);
#pragma unroll
        for (int mt = 0; mt < 4; mt++) {
            const int row = bm + warp_m * 64 + mt * 16 + gr;
            *(float2*)(C + (size_t)row * DD + col) =
                make_float2(acc[mt][nt][0] + bv.x, acc[mt][nt][1] + bv.y);
            *(float2*)(C + (size_t)(row + 8) * DD + col) =
                make_float2(acc[mt][nt][2] + bv.x, acc[mt][nt][3] + bv.y);
        }
    }
}

// ---------------------------------------------------------------------------
// HMMA causal flash attention, all-single-fp16 operands. 2 CTAs/SM.
// BR=128 (8 warps x 16 rows), BC=64. 64 MMAs/tile/warp. 4-deep cp.async.
// Packed ex2.approx.f16x2 for P; row sums via ones-MMA.
// NEW: warps whose rows are entirely masked by causality skip the tile's
// compute (bit-exact: P would be 0, max unchanged, alpha = 1).
// ---------------------------------------------------------------------------
#define AQ_B   18432            // 128*144
#define AARR_B 9216             // 64*144
#define ASTG_B (2 * AARR_B)     // 18432
#define ASMEM_TOTAL (AQ_B + 4 * ASTG_B)   // 92160

__global__ __launch_bounds__(256, 2) void attn_mma_kernel()
{
    extern __shared__ char sm[];
    const uint32_t smb = smem_u32(sm);
    const int tid = threadIdx.x;
    const int w = tid >> 5, lane = tid & 31;
    const int gr = lane >> 2, gc = lane & 3;
    const int qt = (int)gridDim.x - 1 - (int)blockIdx.x;   // long blocks first
    const int h = blockIdx.y, b = blockIdx.z;

    const size_t hb = ((size_t)b * SS) * DD + (size_t)h * HDIM;
    const size_t qrow0 = (size_t)qt * 128;

    const int ntiles = 2 * qt + 2;

    // --- prologue: Q tile (single fp16) ---
#pragma unroll
    for (int i = 0; i < 4; i++) {
        int idx = tid + i * 256;          // 1024 chunks
        int row = idx >> 3, c = idx & 7;
        cp16(smb + row * 144 + c * 16, g_Qh + hb + (qrow0 + row) * DD + c * 8);
    }
    CP_COMMIT();

    auto stage_load = [&](int jt, int s) {
        const uint32_t base = smb + AQ_B + (uint32_t)s * ASTG_B;
#pragma unroll
        for (int i = 0; i < 2; i++) {
            int idx = tid + i * 256;       // 512 chunks per array
            int row = idx >> 3, c = idx & 7;
            cp16(base + row * 144 + c * 16,
                 g_Kh + hb + (size_t)(jt * 64 + row) * DD + c * 8);
            cp16(base + AARR_B + row * 144 + c * 16,
                 g_Vh + hb + (size_t)(jt * 64 + row) * DD + c * 8);
        }
    };
    stage_load(0, 0); CP_COMMIT();
    if (1 < ntiles) stage_load(1, 1);
    CP_COMMIT();
    if (2 < ntiles) stage_load(2, 2);
    CP_COMMIT();

    float m0 = -1e30f, m1 = -1e30f, l0 = 0.f, l1 = 0.f;
    float o[8][4];
#pragma unroll
    for (int d = 0; d < 8; d++)
#pragma unroll
        for (int v = 0; v < 4; v++) o[d][v] = 0.f;

    uint32_t aQ[4][4];
    const int qrow_lo = qt * 128 + w * 16 + gr;
    // This warp's max row: qt*128 + w*16 + 15. Tile jt fully masked for this
    // warp iff jt*64 > that.
    const int warp_row_max = qt * 128 + w * 16 + 15;

    // Q fragments: loop-invariant. Safe after first CP_WAIT(2) below clears
    // the Q group; hoisted via flag-free structure: wait for Q group now
    // (leaves 2 stage groups in flight), then load fragments once.
    CP_WAIT(2);
    __syncthreads();
    {
        const uint32_t qa = smb + (uint32_t)(w * 16 + (lane & 15)) * 144
                            + (lane >> 4) * 16;
#pragma unroll
        for (int kt = 0; kt < 4; kt++) ldsm4(aQ[kt], qa + kt * 32);
    }

    for (int jt = 0; jt < ntiles; jt++) {
        if (jt > 0) {
            CP_WAIT(2);
            __syncthreads();
        }
        if (jt + 3 < ntiles) stage_load(jt + 3, (jt + 3) & 3);
        CP_COMMIT();

        const uint32_t stg = smb + AQ_B + (uint32_t)(jt & 3) * ASTG_B;

        // Warp-level causal skip: all of this warp's rows masked for this tile.
        if (jt * 64 > warp_row_max) continue;

        // ---- S = Q K^T (single fp16) ----
        float sc[8][4];
#pragma unroll
        for (int nt = 0; nt < 8; nt++)
#pragma unroll
            for (int v = 0; v < 4; v++) sc[nt][v] = 0.f;

        const uint32_t kaddr = stg
            + (uint32_t)((lane & 7) | ((lane & 16) >> 1)) * 144 + (lane & 8) * 2;
#pragma unroll
        for (int kt = 0; kt < 4; kt++) {
            uint32_t bK[4][4];
#pragma unroll
            for (int np = 0; np < 4; np++)
                ldsm4(bK[np], kaddr + np * 2304 + kt * 32);
#pragma unroll
            for (int np = 0; np < 4; np++) {
                mma_f16(sc[2*np],   aQ[kt], &bK[np][0]);
                mma_f16(sc[2*np+1], aQ[kt], &bK[np][2]);
            }
        }

        // ---- causal mask (only last two tiles) ----
        if (jt >= 2 * qt) {
#pragma unroll
            for (int nt = 0; nt < 8; nt++) {
                int j = jt * 64 + nt * 8 + gc * 2;
                if (j     > qrow_lo)     sc[nt][0] = -1e30f;
                if (j + 1 > qrow_lo)     sc[nt][1] = -1e30f;
                if (j     > qrow_lo + 8) sc[nt][2] = -1e30f;
                if (j + 1 > qrow_lo + 8) sc[nt][3] = -1e30f;
            }
        }

        // ---- online softmax (exp2 domain) ----
        float mx0 = -1e30f, mx1 = -1e30f;
#pragma unroll
        for (int nt = 0; nt < 8; nt++) {
            mx0 = fmaxf(mx0, fmaxf(sc[nt][0], sc[nt][1]));
            mx1 = fmaxf(mx1, fmaxf(sc[nt][2], sc[nt][3]));
        }
        mx0 = fmaxf(mx0, __shfl_xor_sync(0xffffffffu, mx0, 1));
        mx0 = fmaxf(mx0, __shfl_xor_sync(0xffffffffu, mx0, 2));
        mx1 = fmaxf(mx1, __shfl_xor_sync(0xffffffffu, mx1, 1));
        mx1 = fmaxf(mx1, __shfl_xor_sync(0xffffffffu, mx1, 2));

        float mn0 = fmaxf(m0, mx0), mn1 = fmaxf(m1, mx1);
        float al0 = exp2f(m0 - mn0), al1 = exp2f(m1 - mn1);
        m0 = mn0; m1 = mn1;

        // ---- P = exp2(S - m) computed packed in fp16x2 ----
        uint32_t hP[8][2];
#pragma unroll
        for (int nt = 0; nt < 8; nt++) {
            hP[nt][0] = ex2_f16x2(pack_f16(sc[nt][0] - mn0, sc[nt][1] - mn0));
            hP[nt][1] = ex2_f16x2(pack_f16(sc[nt][2] - mn1, sc[nt][3] - mn1));
        }

        // ---- row sums via ones-MMA: exact fp32, no shuffles ----
        float lacc[4] = {0.f, 0.f, 0.f, 0.f};
        {
            const uint32_t bOnes[2] = {0x3C003C00u, 0x3C003C00u};
#pragma unroll
            for (int kt = 0; kt < 4; kt++) {
                uint32_t aP[4] = {hP[2*kt][0], hP[2*kt][1],
                                  hP[2*kt+1][0], hP[2*kt+1][1]};
                mma_f16(lacc, aP, bOnes);
            }
        }
        l0 = l0 * al0 + lacc[0];
        l1 = l1 * al1 + lacc[2];
#pragma unroll
        for (int d = 0; d < 8; d++) {
            o[d][0] *= al0; o[d][1] *= al0;
            o[d][2] *= al1; o[d][3] *= al1;
        }

        // ---- O += P V (P already packed fp16) ----
        const uint32_t vaddr = stg + AARR_B
            + (uint32_t)(lane & 15) * 144 + (lane >> 4) * 16;
#pragma unroll
        for (int kt = 0; kt < 4; kt++) {
            uint32_t aP[4] = {hP[2*kt][0], hP[2*kt][1],
                              hP[2*kt+1][0], hP[2*kt+1][1]};

            uint32_t bV[4][4];
#pragma unroll
            for (int dp = 0; dp < 4; dp++)
                ldsm4t(bV[dp], vaddr + kt * 2304 + dp * 32);
#pragma unroll
            for (int dp = 0; dp < 4; dp++) {
                mma_f16(o[2*dp],   aP, &bV[dp][0]);
                mma_f16(o[2*dp+1], aP, &bV[dp][2]);
            }
        }
    }

    // ---- epilogue: /l, split to bf16 hi/lo for O-projection ----
    const float inv0 = 1.0f / l0, inv1 = 1.0f / l1;
#pragma unroll
    for (int dt = 0; dt < 8; dt++) {
        size_t idx = hb + (qrow0 + w * 16 + gr) * DD + dt * 8 + gc * 2;
        uint32_t hh, ll;
        cvt_split2(o[dt][0] * inv0, o[dt][1] * inv0, hh, ll);
        *(uint32_t*)&g_Ahi[idx] = hh;
        *(uint32_t*)&g_Alo[idx] = ll;
        size_t idx8 = idx + 8 * DD;
        cvt_split2(o[dt][2] * inv1, o[dt][3] * inv1, hh, ll);
        *(uint32_t*)&g_Ahi[idx8] = hh;
        *(uint32_t*)&g_Alo[idx8] = ll;
    }
}

// ---------------------------------------------------------------------------
extern "C" void kernel_launch(void* const* d_in, const int* in_sizes, int n_in,
                              void* d_out, int out_size)
{
    (void)in_sizes; (void)n_in; (void)out_size;
    const float* x  = (const float*)d_in[0];
    const float* Wq = (const float*)d_in[1];
    const float* bq = (const float*)d_in[2];
    const float* Wk = (const float*)d_in[3];
    const float* bk = (const float*)d_in[4];
    const float* Wv = (const float*)d_in[5];
    const float* bv = (const float*)d_in[6];
    const float* Wo = (const float*)d_in[7];
    const float* bo = (const float*)d_in[8];
    float* out = (float*)d_out;

    __nv_bfloat16 *xh, *xl;
    cudaGetSymbolAddress((void**)&xh, g_xhi);
    cudaGetSymbolAddress((void**)&xl, g_xlo);

    cudaFuncSetAttribute(gemm_qkv_kernel,
                         cudaFuncAttributeMaxDynamicSharedMemorySize, GSMEM_TOTAL);
    cudaFuncSetAttribute(gemm_o_kernel,
                         cudaFuncAttributeMaxDynamicSharedMemorySize, GSMEM_TOTAL);
    cudaFuncSetAttribute(attn_mma_kernel,
                         cudaFuncAttributeMaxDynamicSharedMemorySize, ASMEM_TOTAL);

    prep_kernel<<<12544, 256>>>(x, Wq, Wk, Wv, Wo);

    gemm_qkv_kernel<<<dim3(DD / 128, MM / 128, 3), 256, GSMEM_TOTAL>>>(
        xh, xl, bq, bk, bv);

    attn_mma_kernel<<<dim3(SS / 128, HH, BB), 256, ASMEM_TOTAL>>>();

    gemm_o_kernel<<<dim3(DD / 128, MM / 128), 256, GSMEM_TOTAL>>>(bo, out);
}

// round 15
// speedup vs baseline: 1.1330x; 1.0058x over previous
#include <cuda_runtime.h>
#include <cuda_bf16.h>
#include <cuda_fp16.h>
#include <cstdint>

// Problem constants
#define BB 4
#define SS 2048
#define DD 1024
#define HH 16
#define HDIM 64
#define MM (BB * SS)   // 8192

// log2(e) * 0.125 (softmax scale folded into Q, exp2 domain)
#define QSC 0.18033688011112042f

// ---------------------------------------------------------------------------
// Device-global scratch (allocation-free rule)
// ---------------------------------------------------------------------------
__device__ __nv_bfloat16 g_xhi[(size_t)MM * DD], g_xlo[(size_t)MM * DD];
__device__ __nv_bfloat16 g_Wqh[DD * DD], g_Wql[DD * DD];
__device__ __nv_bfloat16 g_Wkh[DD * DD], g_Wkl[DD * DD];
__device__ __nv_bfloat16 g_Wvh[DD * DD], g_Wvl[DD * DD];
__device__ __nv_bfloat16 g_Woh[DD * DD], g_Wol[DD * DD];
__device__ __half g_Qh[(size_t)MM * DD];    // single fp16 (scaled)
__device__ __half g_Kh[(size_t)MM * DD];    // single fp16
__device__ __half g_Vh[(size_t)MM * DD];    // single fp16
__device__ __nv_bfloat16 g_Ahi[(size_t)MM * DD], g_Alo[(size_t)MM * DD];
__device__ float g_cos[SS * 32];
__device__ float g_sin[SS * 32];

// ---------------------------------------------------------------------------
// PTX helpers (portable sm_80+: ldmatrix, mma.sync, cp.async)
// ---------------------------------------------------------------------------
__device__ __forceinline__ uint32_t smem_u32(const void* p) {
    uint32_t a;
    asm("{ .reg .u64 t; cvta.to.shared.u64 t, %1; cvt.u32.u64 %0, t; }"
        : "=r"(a) : "l"(p));
    return a;
}

__device__ __forceinline__ void ldsm4(uint32_t* r, uint32_t addr) {
    asm volatile("ldmatrix.sync.aligned.m8n8.x4.shared.b16 {%0,%1,%2,%3}, [%4];"
        : "=r"(r[0]), "=r"(r[1]), "=r"(r[2]), "=r"(r[3]) : "r"(addr));
}

__device__ __forceinline__ void ldsm4t(uint32_t* r, uint32_t addr) {
    asm volatile("ldmatrix.sync.aligned.m8n8.x4.trans.shared.b16 {%0,%1,%2,%3}, [%4];"
        : "=r"(r[0]), "=r"(r[1]), "=r"(r[2]), "=r"(r[3]) : "r"(addr));
}

__device__ __forceinline__ void mma_bf16(float* c, const uint32_t* a, const uint32_t* b) {
    asm volatile(
        "mma.sync.aligned.m16n8k16.row.col.f32.bf16.bf16.f32 "
        "{%0,%1,%2,%3}, {%4,%5,%6,%7}, {%8,%9}, {%0,%1,%2,%3};"
        : "+f"(c[0]), "+f"(c[1]), "+f"(c[2]), "+f"(c[3])
        : "r"(a[0]), "r"(a[1]), "r"(a[2]), "r"(a[3]), "r"(b[0]), "r"(b[1]));
}

__device__ __forceinline__ void mma_f16(float* c, const uint32_t* a, const uint32_t* b) {
    asm volatile(
        "mma.sync.aligned.m16n8k16.row.col.f32.f16.f16.f32 "
        "{%0,%1,%2,%3}, {%4,%5,%6,%7}, {%8,%9}, {%0,%1,%2,%3};"
        : "+f"(c[0]), "+f"(c[1]), "+f"(c[2]), "+f"(c[3])
        : "r"(a[0]), "r"(a[1]), "r"(a[2]), "r"(a[3]), "r"(b[0]), "r"(b[1]));
}

__device__ __forceinline__ void cp16(uint32_t dst, const void* src) {
    asm volatile("cp.async.cg.shared.global [%0], [%1], 16;" :: "r"(dst), "l"(src));
}
#define CP_COMMIT() asm volatile("cp.async.commit_group;" ::: "memory")
#define CP_WAIT(n)  asm volatile("cp.async.wait_group %0;" :: "n"(n) : "memory")

// fp32 pair -> packed bf16x2 hi + bf16x2 lo (residual)
__device__ __forceinline__ void cvt_split2(float v0, float v1, uint32_t& h, uint32_t& l) {
    asm("cvt.rn.bf16x2.f32 %0, %1, %2;" : "=r"(h) : "f"(v1), "f"(v0));
    float r0 = v0 - __uint_as_float(h << 16);
    float r1 = v1 - __uint_as_float(h & 0xffff0000u);
    asm("cvt.rn.bf16x2.f32 %0, %1, %2;" : "=r"(l) : "f"(r1), "f"(r0));
}

// fp32 pair -> packed f16x2 (lo half = v0)
__device__ __forceinline__ uint32_t pack_f16(float v0, float v1) {
    uint32_t r;
    asm("cvt.rn.f16x2.f32 %0, %1, %2;" : "=r"(r) : "f"(v1), "f"(v0));
    return r;
}

// packed f16x2 exp2 (approx)
__device__ __forceinline__ uint32_t ex2_f16x2(uint32_t v) {
    asm("ex2.approx.f16x2 %0, %0;" : "+r"(v));
    return v;
}

// ---------------------------------------------------------------------------
// Fused prep: rope tables + x split + 4 weight splits, one launch.
// blocks [0,8192) = x, [8192,12288) = weights (1024 each), [12288,12544) = rope
// ---------------------------------------------------------------------------
__global__ __launch_bounds__(256) void prep_kernel(
    const float* __restrict__ x,
    const float* __restrict__ Wq, const float* __restrict__ Wk,
    const float* __restrict__ Wv, const float* __restrict__ Wo)
{
    const int bid = blockIdx.x;
    const int tid = threadIdx.x;

    if (bid < 8192) {                       // x: 2097152 float4 chunks
        int i = bid * 256 + tid;
        float4 v = ((const float4*)x)[i];
        uint32_t h01, h23, l01, l23;
        cvt_split2(v.x, v.y, h01, l01);
        cvt_split2(v.z, v.w, h23, l23);
        ((uint2*)g_xhi)[i] = make_uint2(h01, h23);
        ((uint2*)g_xlo)[i] = make_uint2(l01, l23);
    } else if (bid < 12288) {               // weights
        int wb = bid - 8192;
        int z = wb >> 10;
        const float* src = (z == 0) ? Wq : (z == 1) ? Wk : (z == 2) ? Wv : Wo;
        __nv_bfloat16* hi = (z == 0) ? g_Wqh : (z == 1) ? g_Wkh : (z == 2) ? g_Wvh : g_Woh;
        __nv_bfloat16* lo = (z == 0) ? g_Wql : (z == 1) ? g_Wkl : (z == 2) ? g_Wvl : g_Wol;
        int i = (wb & 1023) * 256 + tid;
        float4 v = ((const float4*)src)[i];
        uint32_t h01, h23, l01, l23;
        cvt_split2(v.x, v.y, h01, l01);
        cvt_split2(v.z, v.w, h23, l23);
        ((uint2*)hi)[i] = make_uint2(h01, h23);
        ((uint2*)lo)[i] = make_uint2(l01, l23);
    } else {                                // rope tables: S*32 entries
        int idx = (bid - 12288) * 256 + tid;
        int i = idx & 31;
        int s = idx >> 5;
        double inv_freq = exp((double)i * -0.28782313662425575);  // -ln(10000)/32
        double sd, cd;
        sincos((double)s * inv_freq, &sd, &cd);
        g_cos[idx] = (float)cd;
        g_sin[idx] = (float)sd;
    }
}

// ---------------------------------------------------------------------------
// GEMM core (bf16 3-term): 128x128 CTA, 8 warps (64x32), K-chunk 32,
// 2-stage cp.async pipeline, 80 KB smem => 2 CTAs/SM (128 regs cap).
// BANKED configuration (R12): do not modify. Bit-exact path.
// Stage (40960B): Ahi[128x80] | Alo | Whi | Wlo
// ---------------------------------------------------------------------------
#define GARR   10240            // 128 * 80
#define GSTAGE 40960
#define GSMEM_TOTAL (2 * GSTAGE)   // 81920

__device__ __forceinline__ void gemm_core(
    const __nv_bfloat16* const* srcs, uint32_t smb,
    int tid, int wid, int lid, float acc[4][4][4])
{
    const int warp_m = wid & 1, warp_n = wid >> 1;
    const int arow = lid & 15;
    const int ak16 = (lid & 16);
    const int brow = (lid & 7) | ((lid & 16) >> 1);
    const int bk16 = (lid & 8) * 2;
    const uint32_t aBase = smb + (uint32_t)(warp_m * 64 + arow) * 80 + ak16;
    const uint32_t bBase = smb + 2 * GARR
        + (uint32_t)(warp_n * 32 + brow) * 80 + bk16;

    auto issue = [&](int ck) {
        const uint32_t base = smb + (uint32_t)(ck & 1) * GSTAGE;
        const int k0 = ck * 32;
#pragma unroll
        for (int a = 0; a < 4; a++) {
#pragma unroll
            for (int i = 0; i < 2; i++) {
                int idx = tid + i * 256;        // 512 chunks per array
                int row = idx >> 2, q = idx & 3;
                cp16(base + a * GARR + row * 80 + q * 16,
                     srcs[a] + (size_t)row * DD + k0 + q * 8);
            }
        }
    };

    issue(0); CP_COMMIT();
    issue(1); CP_COMMIT();

    const int nchunks = DD / 32;   // 32
    for (int ck = 0; ck < nchunks; ck++) {
        CP_WAIT(1);
        __syncthreads();

        const uint32_t bo = (uint32_t)(ck & 1) * GSTAGE;
#pragma unroll
        for (int kk = 0; kk < 2; kk++) {
            uint32_t af[4][4], bf[2][4], bf2[2][4];
            const uint32_t ka = aBase + bo + kk * 32;
            const uint32_t kb = bBase + bo + kk * 32;
            // hi operands
#pragma unroll
            for (int mt = 0; mt < 4; mt++) ldsm4(af[mt], ka + mt * 1280);
#pragma unroll
            for (int p = 0; p < 2; p++)  ldsm4(bf[p], kb + p * 1280);
            // term hi*hi
#pragma unroll
            for (int mt = 0; mt < 4; mt++)
#pragma unroll
                for (int nt = 0; nt < 4; nt++)
                    mma_bf16(acc[mt][nt], af[mt], &bf[nt >> 1][(nt & 1) * 2]);
            // term hi*lo
#pragma unroll
            for (int p = 0; p < 2; p++)  ldsm4(bf2[p], kb + GARR + p * 1280);
#pragma unroll
            for (int mt = 0; mt < 4; mt++)
#pragma unroll
                for (int nt = 0; nt < 4; nt++)
                    mma_bf16(acc[mt][nt], af[mt], &bf2[nt >> 1][(nt & 1) * 2]);
            // term lo*hi (af overwritten with Alo)
#pragma unroll
            for (int mt = 0; mt < 4; mt++) ldsm4(af[mt], ka + GARR + mt * 1280);
#pragma unroll
            for (int mt = 0; mt < 4; mt++)
#pragma unroll
                for (int nt = 0; nt < 4; nt++)
                    mma_bf16(acc[mt][nt], af[mt], &bf[nt >> 1][(nt & 1) * 2]);
        }
        __syncthreads();
        if (ck + 2 < nchunks) issue(ck + 2);
        CP_COMMIT();
    }
}

// ---------------------------------------------------------------------------
// Fused QKV GEMM: z = 0:Q, 1:K, 2:V.  Epilogue fuses RoPE + fp16 store.
// ---------------------------------------------------------------------------
__global__ __launch_bounds__(256, 2) void gemm_qkv_kernel(
    const __nv_bfloat16* __restrict__ xh, const __nv_bfloat16* __restrict__ xl,
    const float* __restrict__ bq, const float* __restrict__ bk,
    const float* __restrict__ bv)
{
    extern __shared__ char sm[];
    const uint32_t smb = smem_u32(sm);
    const int tid = threadIdx.x;
    const int wid = tid >> 5, lid = tid & 31;
    const int bm = blockIdx.y * 128, bn = blockIdx.x * 128;
    const int z = blockIdx.z;
    const int warp_m = wid & 1, warp_n = wid >> 1;

    const __nv_bfloat16* Whi = (z == 0) ? g_Wqh : (z == 1) ? g_Wkh : g_Wvh;
    const __nv_bfloat16* Wlo = (z == 0) ? g_Wql : (z == 1) ? g_Wkl : g_Wvl;
    const float* bias = (z == 0) ? bq : (z == 1) ? bk : bv;

    const __nv_bfloat16* srcs[4] = {
        xh + (size_t)bm * DD, xl + (size_t)bm * DD,
        Whi + (size_t)bn * DD, Wlo + (size_t)bn * DD };

    float acc[4][4][4];
#pragma unroll
    for (int i = 0; i < 4; i++)
#pragma unroll
        for (int j = 0; j < 4; j++)
#pragma unroll
            for (int v = 0; v < 4; v++) acc[i][j][v] = 0.f;

    gemm_core(srcs, smb, tid, wid, lid, acc);

    const int gr = lid >> 2, gc = lid & 3;

    if (z == 2) {
        // V: direct single-fp16 store (+bias)
#pragma unroll
        for (int nt = 0; nt < 4; nt++) {
            const int col = bn + warp_n * 32 + nt * 8 + gc * 2;
            const float2 bv2 = *(const float2*)(bias + col);
#pragma unroll
            for (int mt = 0; mt < 4; mt++) {
                const int row = bm + warp_m * 64 + mt * 16 + gr;
                *(uint32_t*)&g_Vh[(size_t)row * DD + col] =
                    pack_f16(acc[mt][nt][0] + bv2.x, acc[mt][nt][1] + bv2.y);
                *(uint32_t*)&g_Vh[(size_t)(row + 8) * DD + col] =
                    pack_f16(acc[mt][nt][2] + bv2.x, acc[mt][nt][3] + bv2.y);
            }
        }
        return;
    }

    // Q/K: stage to smem (+bias), then RoPE across (i, i+32) pairs.
    CP_WAIT(0);
    __syncthreads();
    float* Ds = (float*)sm;    // [128][132] = 67584 B < 81920
#pragma unroll
    for (int nt = 0; nt < 4; nt++) {
        const int cl = warp_n * 32 + nt * 8 + gc * 2;
        const float2 bv2 = *(const float2*)(bias + bn + cl);
#pragma unroll
        for (int mt = 0; mt < 4; mt++) {
            const int rl = warp_m * 64 + mt * 16 + gr;
            Ds[rl * 132 + cl]     = acc[mt][nt][0] + bv2.x;
            Ds[rl * 132 + cl + 1] = acc[mt][nt][1] + bv2.y;
            Ds[(rl + 8) * 132 + cl]     = acc[mt][nt][2] + bv2.x;
            Ds[(rl + 8) * 132 + cl + 1] = acc[mt][nt][3] + bv2.y;
        }
    }
    __syncthreads();

    for (int u = tid; u < 128 * 32; u += 256) {
        const int row = u >> 5, t = u & 31;
        const int hl = t >> 4, tt = t & 15;
        const int col = hl * 64 + tt * 2;
        const int s = (bm + row) & (SS - 1);
        const int i0 = tt * 2;
        const float cs0 = g_cos[s * 32 + i0], sn0 = g_sin[s * 32 + i0];
        const float cs1 = g_cos[s * 32 + i0 + 1], sn1 = g_sin[s * 32 + i0 + 1];
        const float v1a = Ds[row * 132 + col],      v1b = Ds[row * 132 + col + 1];
        const float v2a = Ds[row * 132 + col + 32], v2b = Ds[row * 132 + col + 33];
        const float r1a = v1a * cs0 - v2a * sn0, r2a = v2a * cs0 + v1a * sn0;
        const float r1b = v1b * cs1 - v2b * sn1, r2b = v2b * cs1 + v1b * sn1;
        const size_t out = (size_t)(bm + row) * DD + bn + col;
        if (z == 0) {
            *(uint32_t*)&g_Qh[out]      = pack_f16(r1a * QSC, r1b * QSC);
            *(uint32_t*)&g_Qh[out + 32] = pack_f16(r2a * QSC, r2b * QSC);
        } else {
            *(uint32_t*)&g_Kh[out]      = pack_f16(r1a, r1b);
            *(uint32_t*)&g_Kh[out + 32] = pack_f16(r2a, r2b);
        }
    }
}

// ---------------------------------------------------------------------------
// O-projection GEMM: out = A @ Wo^T + bo, fp32 out.
// ---------------------------------------------------------------------------
__global__ __launch_bounds__(256, 2) void gemm_o_kernel(
    const float* __restrict__ bias, float* __restrict__ C)
{
    extern __shared__ char sm[];
    const uint32_t smb = smem_u32(sm);
    const int tid = threadIdx.x;
    const int wid = tid >> 5, lid = tid & 31;
    const int bm = blockIdx.y * 128, bn = blockIdx.x * 128;
    const int warp_m = wid & 1, warp_n = wid >> 1;

    const __nv_bfloat16* srcs[4] = {
        g_Ahi + (size_t)bm * DD, g_Alo + (size_t)bm * DD,
        g_Woh + (size_t)bn * DD, g_Wol + (size_t)bn * DD };

    float acc[4][4][4];
#pragma unroll
    for (int i = 0; i < 4; i++)
#pragma unroll
        for (int j = 0; j < 4; j++)
#pragma unroll
            for (int v = 0; v < 4; v++) acc[i][j][v] = 0.f;

    gemm_core(srcs, smb, tid, wid, lid, acc);

    const int gr = lid >> 2, gc = lid & 3;
#pragma unroll
    for (int nt = 0; nt < 4; nt++) {
        const int col = bn + warp_n * 32 + nt * 8 + gc * 2;
        const float2 bv = *(const float2*)(bias + col);
#pragma unroll
        for (int mt = 0; mt < 4; mt++) {
            const int row = bm + warp_m * 64 + mt * 16 + gr;
            *(float2*)(C + (size_t)row * DD + col) =
                make_float2(acc[mt][nt][0] + bv.x, acc[mt][nt][1] + bv.y);
            *(float2*)(C + (size_t)(row + 8) * DD + col) =
                make_float2(acc[mt][nt][2] + bv.x, acc[mt][nt][3] + bv.y);
        }
    }
}

// ---------------------------------------------------------------------------
// HMMA causal flash attention, all-single-fp16 operands. 2 CTAs/SM.
// BR=128 (8 warps x 16 rows), BC=64. 64 MMAs/tile/warp. 4 stage buffers.
// Packed ex2.approx.f16x2 for P; row sums via ones-MMA; warp causal skip.
// NEW: TWO K-tiles per pipeline step -> barrier count halved (bit-exact:
// per-tile math and ordering unchanged; ntiles = 2qt+2 is always even).
// ---------------------------------------------------------------------------
#define AQ_B   18432            // 128*144
#define AARR_B 9216             // 64*144
#define ASTG_B (2 * AARR_B)     // 18432
#define ASMEM_TOTAL (AQ_B + 4 * ASTG_B)   // 92160

__global__ __launch_bounds__(256, 2) void attn_mma_kernel()
{
    extern __shared__ char sm[];
    const uint32_t smb = smem_u32(sm);
    const int tid = threadIdx.x;
    const int w = tid >> 5, lane = tid & 31;
    const int gr = lane >> 2, gc = lane & 3;
    const int qt = (int)gridDim.x - 1 - (int)blockIdx.x;   // long blocks first
    const int h = blockIdx.y, b = blockIdx.z;

    const size_t hb = ((size_t)b * SS) * DD + (size_t)h * HDIM;
    const size_t qrow0 = (size_t)qt * 128;

    const int ntiles = 2 * qt + 2;          // always even

    // --- prologue: Q tile (single fp16) ---
#pragma unroll
    for (int i = 0; i < 4; i++) {
        int idx = tid + i * 256;          // 1024 chunks
        int row = idx >> 3, c = idx & 7;
        cp16(smb + row * 144 + c * 16, g_Qh + hb + (qrow0 + row) * DD + c * 8);
    }
    CP_COMMIT();

    auto stage_load = [&](int jt, int s) {
        const uint32_t base = smb + AQ_B + (uint32_t)s * ASTG_B;
#pragma unroll
        for (int i = 0; i < 2; i++) {
            int idx = tid + i * 256;       // 512 chunks per array
            int row = idx >> 3, c = idx & 7;
            cp16(base + row * 144 + c * 16,
                 g_Kh + hb + (size_t)(jt * 64 + row) * DD + c * 8);
            cp16(base + AARR_B + row * 144 + c * 16,
                 g_Vh + hb + (size_t)(jt * 64 + row) * DD + c * 8);
        }
    };
    stage_load(0, 0); CP_COMMIT();
    stage_load(1, 1); CP_COMMIT();

    float m0 = -1e30f, m1 = -1e30f, l0 = 0.f, l1 = 0.f;
    float o[8][4];
#pragma unroll
    for (int d = 0; d < 8; d++)
#pragma unroll
        for (int v = 0; v < 4; v++) o[d][v] = 0.f;

    uint32_t aQ[4][4];
    const int qrow_lo = qt * 128 + w * 16 + gr;
    const int warp_row_max = qt * 128 + w * 16 + 15;

    // One warp-tile of attention for K-tile jt (buffers assumed resident).
    auto process_tile = [&](int jt) {
        if (jt * 64 > warp_row_max) return;   // fully causally masked

        const uint32_t stg = smb + AQ_B + (uint32_t)(jt & 3) * ASTG_B;

        // ---- S = Q K^T (single fp16) ----
        float sc[8][4];
#pragma unroll
        for (int nt = 0; nt < 8; nt++)
#pragma unroll
            for (int v = 0; v < 4; v++) sc[nt][v] = 0.f;

        const uint32_t kaddr = stg
            + (uint32_t)((lane & 7) | ((lane & 16) >> 1)) * 144 + (lane & 8) * 2;
#pragma unroll
        for (int kt = 0; kt < 4; kt++) {
            uint32_t bK[4][4];
#pragma unroll
            for (int np = 0; np < 4; np++)
                ldsm4(bK[np], kaddr + np * 2304 + kt * 32);
#pragma unroll
            for (int np = 0; np < 4; np++) {
                mma_f16(sc[2*np],   aQ[kt], &bK[np][0]);
                mma_f16(sc[2*np+1], aQ[kt], &bK[np][2]);
            }
        }

        // ---- causal mask (only last two tiles) ----
        if (jt >= 2 * qt) {
#pragma unroll
            for (int nt = 0; nt < 8; nt++) {
                int j = jt * 64 + nt * 8 + gc * 2;
                if (j     > qrow_lo)     sc[nt][0] = -1e30f;
                if (j + 1 > qrow_lo)     sc[nt][1] = -1e30f;
                if (j     > qrow_lo + 8) sc[nt][2] = -1e30f;
                if (j + 1 > qrow_lo + 8) sc[nt][3] = -1e30f;
            }
        }

        // ---- online softmax (exp2 domain) ----
        float mx0 = -1e30f, mx1 = -1e30f;
#pragma unroll
        for (int nt = 0; nt < 8; nt++) {
            mx0 = fmaxf(mx0, fmaxf(sc[nt][0], sc[nt][1]));
            mx1 = fmaxf(mx1, fmaxf(sc[nt][2], sc[nt][3]));
        }
        mx0 = fmaxf(mx0, __shfl_xor_sync(0xffffffffu, mx0, 1));
        mx0 = fmaxf(mx0, __shfl_xor_sync(0xffffffffu, mx0, 2));
        mx1 = fmaxf(mx1, __shfl_xor_sync(0xffffffffu, mx1, 1));
        mx1 = fmaxf(mx1, __shfl_xor_sync(0xffffffffu, mx1, 2));

        float mn0 = fmaxf(m0, mx0), mn1 = fmaxf(m1, mx1);
        float al0 = exp2f(m0 - mn0), al1 = exp2f(m1 - mn1);
        m0 = mn0; m1 = mn1;

        // ---- P = exp2(S - m) computed packed in fp16x2 ----
        uint32_t hP[8][2];
#pragma unroll
        for (int nt = 0; nt < 8; nt++) {
            hP[nt][0] = ex2_f16x2(pack_f16(sc[nt][0] - mn0, sc[nt][1] - mn0));
            hP[nt][1] = ex2_f16x2(pack_f16(sc[nt][2] - mn1, sc[nt][3] - mn1));
        }

        // ---- row sums via ones-MMA: exact fp32, no shuffles ----
        float lacc[4] = {0.f, 0.f, 0.f, 0.f};
        {
            const uint32_t bOnes[2] = {0x3C003C00u, 0x3C003C00u};
#pragma unroll
            for (int kt = 0; kt < 4; kt++) {
                uint32_t aP[4] = {hP[2*kt][0], hP[2*kt][1],
                                  hP[2*kt+1][0], hP[2*kt+1][1]};
                mma_f16(lacc, aP, bOnes);
            }
        }
        l0 = l0 * al0 + lacc[0];
        l1 = l1 * al1 + lacc[2];
#pragma unroll
        for (int d = 0; d < 8; d++) {
            o[d][0] *= al0; o[d][1] *= al0;
            o[d][2] *= al1; o[d][3] *= al1;
        }

        // ---- O += P V (P already packed fp16) ----
        const uint32_t vaddr = stg + AARR_B
            + (uint32_t)(lane & 15) * 144 + (lane >> 4) * 16;
#pragma unroll
        for (int kt = 0; kt < 4; kt++) {
            uint32_t aP[4] = {hP[2*kt][0], hP[2*kt][1],
                              hP[2*kt+1][0], hP[2*kt+1][1]};

            uint32_t bV[4][4];
#pragma unroll
            for (int dp = 0; dp < 4; dp++)
                ldsm4t(bV[dp], vaddr + kt * 2304 + dp * 32);
#pragma unroll
            for (int dp = 0; dp < 4; dp++) {
                mma_f16(o[2*dp],   aP, &bV[dp][0]);
                mma_f16(o[2*dp+1], aP, &bV[dp][2]);
            }
        }
    };

    // Main loop: two K-tiles per pipeline step. One wait + one barrier per
    // pair. Issues for tiles t+2, t+3 go into the buffers processed in the
    // PREVIOUS iteration (safe: the barrier just passed covers them).
    const int npairs = ntiles >> 1;
    for (int ip = 0; ip < npairs; ip++) {
        const int t0 = 2 * ip;
        CP_WAIT(0);
        __syncthreads();

        if (ip == 0) {   // Q fragments (loop-invariant; Q group completed)
            const uint32_t qa = smb + (uint32_t)(w * 16 + (lane & 15)) * 144
                                + (lane >> 4) * 16;
#pragma unroll
            for (int kt = 0; kt < 4; kt++) ldsm4(aQ[kt], qa + kt * 32);
        }

        if (t0 + 2 < ntiles) { stage_load(t0 + 2, (t0 + 2) & 3); CP_COMMIT(); }
        if (t0 + 3 < ntiles) { stage_load(t0 + 3, (t0 + 3) & 3); CP_COMMIT(); }

        process_tile(t0);
        process_tile(t0 + 1);
    }

    // ---- epilogue: /l, split to bf16 hi/lo for O-projection ----
    const float inv0 = 1.0f / l0, inv1 = 1.0f / l1;
#pragma unroll
    for (int dt = 0; dt < 8; dt++) {
        size_t idx = hb + (qrow0 + w * 16 + gr) * DD + dt * 8 + gc * 2;
        uint32_t hh, ll;
        cvt_split2(o[dt][0] * inv0, o[dt][1] * inv0, hh, ll);
        *(uint32_t*)&g_Ahi[idx] = hh;
        *(uint32_t*)&g_Alo[idx] = ll;
        size_t idx8 = idx + 8 * DD;
        cvt_split2(o[dt][2] * inv1, o[dt][3] * inv1, hh, ll);
        *(uint32_t*)&g_Ahi[idx8] = hh;
        *(uint32_t*)&g_Alo[idx8] = ll;
    }
}

// ---------------------------------------------------------------------------
extern "C" void kernel_launch(void* const* d_in, const int* in_sizes, int n_in,
                              void* d_out, int out_size)
{
    (void)in_sizes; (void)n_in; (void)out_size;
    const float* x  = (const float*)d_in[0];
    const float* Wq = (const float*)d_in[1];
    const float* bq = (const float*)d_in[2];
    const float* Wk = (const float*)d_in[3];
    const float* bk = (const float*)d_in[4];
    const float* Wv = (const float*)d_in[5];
    const float* bv = (const float*)d_in[6];
    const float* Wo = (const float*)d_in[7];
    const float* bo = (const float*)d_in[8];
    float* out = (float*)d_out;

    __nv_bfloat16 *xh, *xl;
    cudaGetSymbolAddress((void**)&xh, g_xhi);
    cudaGetSymbolAddress((void**)&xl, g_xlo);

    cudaFuncSetAttribute(gemm_qkv_kernel,
                         cudaFuncAttributeMaxDynamicSharedMemorySize, GSMEM_TOTAL);
    cudaFuncSetAttribute(gemm_o_kernel,
                         cudaFuncAttributeMaxDynamicSharedMemorySize, GSMEM_TOTAL);
    cudaFuncSetAttribute(attn_mma_kernel,
                         cudaFuncAttributeMaxDynamicSharedMemorySize, ASMEM_TOTAL);

    prep_kernel<<<12544, 256>>>(x, Wq, Wk, Wv, Wo);

    gemm_qkv_kernel<<<dim3(DD / 128, MM / 128, 3), 256, GSMEM_TOTAL>>>(
        xh, xl, bq, bk, bv);

    attn_mma_kernel<<<dim3(SS / 128, HH, BB), 256, ASMEM_TOTAL>>>();

    gemm_o_kernel<<<dim3(DD / 128, MM / 128), 256, GSMEM_TOTAL>>>(bo, out);
}

// round 16
// speedup vs baseline: 1.1420x; 1.0079x over previous
#include <cuda_runtime.h>
#include <cuda_bf16.h>
#include <cuda_fp16.h>
#include <cstdint>

// Problem constants
#define BB 4
#define SS 2048
#define DD 1024
#define HH 16
#define HDIM 64
#define MM (BB * SS)   // 8192

// log2(e) * 0.125 (softmax scale folded into Q, exp2 domain)
#define QSC 0.18033688011112042f

// ---------------------------------------------------------------------------
// Device-global scratch (allocation-free rule)
// ---------------------------------------------------------------------------
__device__ __nv_bfloat16 g_xhi[(size_t)MM * DD], g_xlo[(size_t)MM * DD];
__device__ __nv_bfloat16 g_Wqh[DD * DD], g_Wql[DD * DD];
__device__ __nv_bfloat16 g_Wkh[DD * DD], g_Wkl[DD * DD];
__device__ __nv_bfloat16 g_Wvh[DD * DD], g_Wvl[DD * DD];
__device__ __nv_bfloat16 g_Woh[DD * DD], g_Wol[DD * DD];
__device__ __half g_Qh[(size_t)MM * DD];    // single fp16 (scaled)
__device__ __half g_Kh[(size_t)MM * DD];    // single fp16
__device__ __half g_Vh[(size_t)MM * DD];    // single fp16
__device__ __nv_bfloat16 g_Ahi[(size_t)MM * DD], g_Alo[(size_t)MM * DD];
__device__ float g_cos[SS * 32];
__device__ float g_sin[SS * 32];

// ---------------------------------------------------------------------------
// PTX helpers (portable sm_80+: ldmatrix, mma.sync, cp.async)
// ---------------------------------------------------------------------------
__device__ __forceinline__ uint32_t smem_u32(const void* p) {
    uint32_t a;
    asm("{ .reg .u64 t; cvta.to.shared.u64 t, %1; cvt.u32.u64 %0, t; }"
        : "=r"(a) : "l"(p));
    return a;
}

__device__ __forceinline__ void ldsm4(uint32_t* r, uint32_t addr) {
    asm volatile("ldmatrix.sync.aligned.m8n8.x4.shared.b16 {%0,%1,%2,%3}, [%4];"
        : "=r"(r[0]), "=r"(r[1]), "=r"(r[2]), "=r"(r[3]) : "r"(addr));
}

__device__ __forceinline__ void ldsm4t(uint32_t* r, uint32_t addr) {
    asm volatile("ldmatrix.sync.aligned.m8n8.x4.trans.shared.b16 {%0,%1,%2,%3}, [%4];"
        : "=r"(r[0]), "=r"(r[1]), "=r"(r[2]), "=r"(r[3]) : "r"(addr));
}

__device__ __forceinline__ void mma_bf16(float* c, const uint32_t* a, const uint32_t* b) {
    asm volatile(
        "mma.sync.aligned.m16n8k16.row.col.f32.bf16.bf16.f32 "
        "{%0,%1,%2,%3}, {%4,%5,%6,%7}, {%8,%9}, {%0,%1,%2,%3};"
        : "+f"(c[0]), "+f"(c[1]), "+f"(c[2]), "+f"(c[3])
        : "r"(a[0]), "r"(a[1]), "r"(a[2]), "r"(a[3]), "r"(b[0]), "r"(b[1]));
}

__device__ __forceinline__ void mma_f16(float* c, const uint32_t* a, const uint32_t* b) {
    asm volatile(
        "mma.sync.aligned.m16n8k16.row.col.f32.f16.f16.f32 "
        "{%0,%1,%2,%3}, {%4,%5,%6,%7}, {%8,%9}, {%0,%1,%2,%3};"
        : "+f"(c[0]), "+f"(c[1]), "+f"(c[2]), "+f"(c[3])
        : "r"(a[0]), "r"(a[1]), "r"(a[2]), "r"(a[3]), "r"(b[0]), "r"(b[1]));
}

__device__ __forceinline__ void cp16(uint32_t dst, const void* src) {
    asm volatile("cp.async.cg.shared.global [%0], [%1], 16;" :: "r"(dst), "l"(src));
}
#define CP_COMMIT() asm volatile("cp.async.commit_group;" ::: "memory")
#define CP_WAIT(n)  asm volatile("cp.async.wait_group %0;" :: "n"(n) : "memory")

// fp32 pair -> packed bf16x2 hi + bf16x2 lo (residual)
__device__ __forceinline__ void cvt_split2(float v0, float v1, uint32_t& h, uint32_t& l) {
    asm("cvt.rn.bf16x2.f32 %0, %1, %2;" : "=r"(h) : "f"(v1), "f"(v0));
    float r0 = v0 - __uint_as_float(h << 16);
    float r1 = v1 - __uint_as_float(h & 0xffff0000u);
    asm("cvt.rn.bf16x2.f32 %0, %1, %2;" : "=r"(l) : "f"(r1), "f"(r0));
}

// fp32 pair -> packed f16x2 (lo half = v0)
__device__ __forceinline__ uint32_t pack_f16(float v0, float v1) {
    uint32_t r;
    asm("cvt.rn.f16x2.f32 %0, %1, %2;" : "=r"(r) : "f"(v1), "f"(v0));
    return r;
}

// packed f16x2 exp2 (approx)
__device__ __forceinline__ uint32_t ex2_f16x2(uint32_t v) {
    asm("ex2.approx.f16x2 %0, %0;" : "+r"(v));
    return v;
}

// ---------------------------------------------------------------------------
// Fused prep: rope tables + x split + 4 weight splits, one launch.
// blocks [0,8192) = x, [8192,12288) = weights (1024 each), [12288,12544) = rope
// ---------------------------------------------------------------------------
__global__ __launch_bounds__(256) void prep_kernel(
    const float* __restrict__ x,
    const float* __restrict__ Wq, const float* __restrict__ Wk,
    const float* __restrict__ Wv, const float* __restrict__ Wo)
{
    const int bid = blockIdx.x;
    const int tid = threadIdx.x;

    if (bid < 8192) {                       // x: 2097152 float4 chunks
        int i = bid * 256 + tid;
        float4 v = ((const float4*)x)[i];
        uint32_t h01, h23, l01, l23;
        cvt_split2(v.x, v.y, h01, l01);
        cvt_split2(v.z, v.w, h23, l23);
        ((uint2*)g_xhi)[i] = make_uint2(h01, h23);
        ((uint2*)g_xlo)[i] = make_uint2(l01, l23);
    } else if (bid < 12288) {               // weights
        int wb = bid - 8192;
        int z = wb >> 10;
        const float* src = (z == 0) ? Wq : (z == 1) ? Wk : (z == 2) ? Wv : Wo;
        __nv_bfloat16* hi = (z == 0) ? g_Wqh : (z == 1) ? g_Wkh : (z == 2) ? g_Wvh : g_Woh;
        __nv_bfloat16* lo = (z == 0) ? g_Wql : (z == 1) ? g_Wkl : (z == 2) ? g_Wvl : g_Wol;
        int i = (wb & 1023) * 256 + tid;
        float4 v = ((const float4*)src)[i];
        uint32_t h01, h23, l01, l23;
        cvt_split2(v.x, v.y, h01, l01);
        cvt_split2(v.z, v.w, h23, l23);
        ((uint2*)hi)[i] = make_uint2(h01, h23);
        ((uint2*)lo)[i] = make_uint2(l01, l23);
    } else {                                // rope tables: S*32 entries
        int idx = (bid - 12288) * 256 + tid;
        int i = idx & 31;
        int s = idx >> 5;
        double inv_freq = exp((double)i * -0.28782313662425575);  // -ln(10000)/32
        double sd, cd;
        sincos((double)s * inv_freq, &sd, &cd);
        g_cos[idx] = (float)cd;
        g_sin[idx] = (float)sd;
    }
}

// ---------------------------------------------------------------------------
// GEMM core (bf16 3-term): 128x128 CTA, 8 warps (64x32), K-chunk 32,
// 2-stage cp.async pipeline, 80 KB smem => 2 CTAs/SM (128 regs cap).
// BANKED configuration (R12): do not modify. Bit-exact path.
// Stage (40960B): Ahi[128x80] | Alo | Whi | Wlo
// ---------------------------------------------------------------------------
#define GARR   10240            // 128 * 80
#define GSTAGE 40960
#define GSMEM_TOTAL (2 * GSTAGE)   // 81920

__device__ __forceinline__ void gemm_core(
    const __nv_bfloat16* const* srcs, uint32_t smb,
    int tid, int wid, int lid, float acc[4][4][4])
{
    const int warp_m = wid & 1, warp_n = wid >> 1;
    const int arow = lid & 15;
    const int ak16 = (lid & 16);
    const int brow = (lid & 7) | ((lid & 16) >> 1);
    const int bk16 = (lid & 8) * 2;
    const uint32_t aBase = smb + (uint32_t)(warp_m * 64 + arow) * 80 + ak16;
    const uint32_t bBase = smb + 2 * GARR
        + (uint32_t)(warp_n * 32 + brow) * 80 + bk16;

    auto issue = [&](int ck) {
        const uint32_t base = smb + (uint32_t)(ck & 1) * GSTAGE;
        const int k0 = ck * 32;
#pragma unroll
        for (int a = 0; a < 4; a++) {
#pragma unroll
            for (int i = 0; i < 2; i++) {
                int idx = tid + i * 256;        // 512 chunks per array
                int row = idx >> 2, q = idx & 3;
                cp16(base + a * GARR + row * 80 + q * 16,
                     srcs[a] + (size_t)row * DD + k0 + q * 8);
            }
        }
    };

    issue(0); CP_COMMIT();
    issue(1); CP_COMMIT();

    const int nchunks = DD / 32;   // 32
    for (int ck = 0; ck < nchunks; ck++) {
        CP_WAIT(1);
        __syncthreads();

        const uint32_t bo = (uint32_t)(ck & 1) * GSTAGE;
#pragma unroll
        for (int kk = 0; kk < 2; kk++) {
            uint32_t af[4][4], bf[2][4], bf2[2][4];
            const uint32_t ka = aBase + bo + kk * 32;
            const uint32_t kb = bBase + bo + kk * 32;
            // hi operands
#pragma unroll
            for (int mt = 0; mt < 4; mt++) ldsm4(af[mt], ka + mt * 1280);
#pragma unroll
            for (int p = 0; p < 2; p++)  ldsm4(bf[p], kb + p * 1280);
            // term hi*hi
#pragma unroll
            for (int mt = 0; mt < 4; mt++)
#pragma unroll
                for (int nt = 0; nt < 4; nt++)
                    mma_bf16(acc[mt][nt], af[mt], &bf[nt >> 1][(nt & 1) * 2]);
            // term hi*lo
#pragma unroll
            for (int p = 0; p < 2; p++)  ldsm4(bf2[p], kb + GARR + p * 1280);
#pragma unroll
            for (int mt = 0; mt < 4; mt++)
#pragma unroll
                for (int nt = 0; nt < 4; nt++)
                    mma_bf16(acc[mt][nt], af[mt], &bf2[nt >> 1][(nt & 1) * 2]);
            // term lo*hi (af overwritten with Alo)
#pragma unroll
            for (int mt = 0; mt < 4; mt++) ldsm4(af[mt], ka + GARR + mt * 1280);
#pragma unroll
            for (int mt = 0; mt < 4; mt++)
#pragma unroll
                for (int nt = 0; nt < 4; nt++)
                    mma_bf16(acc[mt][nt], af[mt], &bf[nt >> 1][(nt & 1) * 2]);
        }
        __syncthreads();
        if (ck + 2 < nchunks) issue(ck + 2);
        CP_COMMIT();
    }
}

// ---------------------------------------------------------------------------
// Fused QKV GEMM: z = 0:Q, 1:K, 2:V.  Epilogue fuses RoPE + fp16 store.
// ---------------------------------------------------------------------------
__global__ __launch_bounds__(256, 2) void gemm_qkv_kernel(
    const __nv_bfloat16* __restrict__ xh, const __nv_bfloat16* __restrict__ xl,
    const float* __restrict__ bq, const float* __restrict__ bk,
    const float* __restrict__ bv)
{
    extern __shared__ char sm[];
    const uint32_t smb = smem_u32(sm);
    const int tid = threadIdx.x;
    const int wid = tid >> 5, lid = tid & 31;
    const int bm = blockIdx.y * 128, bn = blockIdx.x * 128;
    const int z = blockIdx.z;
    const int warp_m = wid & 1, warp_n = wid >> 1;

    const __nv_bfloat16* Whi = (z == 0) ? g_Wqh : (z == 1) ? g_Wkh : g_Wvh;
    const __nv_bfloat16* Wlo = (z == 0) ? g_Wql : (z == 1) ? g_Wkl : g_Wvl;
    const float* bias = (z == 0) ? bq : (z == 1) ? bk : bv;

    const __nv_bfloat16* srcs[4] = {
        xh + (size_t)bm * DD, xl + (size_t)bm * DD,
        Whi + (size_t)bn * DD, Wlo + (size_t)bn * DD };

    float acc[4][4][4];
#pragma unroll
    for (int i = 0; i < 4; i++)
#pragma unroll
        for (int j = 0; j < 4; j++)
#pragma unroll
            for (int v = 0; v < 4; v++) acc[i][j][v] = 0.f;

    gemm_core(srcs, smb, tid, wid, lid, acc);

    const int gr = lid >> 2, gc = lid & 3;

    if (z == 2) {
        // V: direct single-fp16 store (+bias)
#pragma unroll
        for (int nt = 0; nt < 4; nt++) {
            const int col = bn + warp_n * 32 + nt * 8 + gc * 2;
            const float2 bv2 = *(const float2*)(bias + col);
#pragma unroll
            for (int mt = 0; mt < 4; mt++) {
                const int row = bm + warp_m * 64 + mt * 16 + gr;
                *(uint32_t*)&g_Vh[(size_t)row * DD + col] =
                    pack_f16(acc[mt][nt][0] + bv2.x, acc[mt][nt][1] + bv2.y);
                *(uint32_t*)&g_Vh[(size_t)(row + 8) * DD + col] =
                    pack_f16(acc[mt][nt][2] + bv2.x, acc[mt][nt][3] + bv2.y);
            }
        }
        return;
    }

    // Q/K: stage to smem (+bias), then RoPE across (i, i+32) pairs.
    CP_WAIT(0);
    __syncthreads();
    float* Ds = (float*)sm;    // [128][132] = 67584 B < 81920
#pragma unroll
    for (int nt = 0; nt < 4; nt++) {
        const int cl = warp_n * 32 + nt * 8 + gc * 2;
        const float2 bv2 = *(const float2*)(bias + bn + cl);
#pragma unroll
        for (int mt = 0; mt < 4; mt++) {
            const int rl = warp_m * 64 + mt * 16 + gr;
            Ds[rl * 132 + cl]     = acc[mt][nt][0] + bv2.x;
            Ds[rl * 132 + cl + 1] = acc[mt][nt][1] + bv2.y;
            Ds[(rl + 8) * 132 + cl]     = acc[mt][nt][2] + bv2.x;
            Ds[(rl + 8) * 132 + cl + 1] = acc[mt][nt][3] + bv2.y;
        }
    }
    __syncthreads();

    for (int u = tid; u < 128 * 32; u += 256) {
        const int row = u >> 5, t = u & 31;
        const int hl = t >> 4, tt = t & 15;
        const int col = hl * 64 + tt * 2;
        const int s = (bm + row) & (SS - 1);
        const int i0 = tt * 2;
        const float cs0 = g_cos[s * 32 + i0], sn0 = g_sin[s * 32 + i0];
        const float cs1 = g_cos[s * 32 + i0 + 1], sn1 = g_sin[s * 32 + i0 + 1];
        const float v1a = Ds[row * 132 + col],      v1b = Ds[row * 132 + col + 1];
        const float v2a = Ds[row * 132 + col + 32], v2b = Ds[row * 132 + col + 33];
        const float r1a = v1a * cs0 - v2a * sn0, r2a = v2a * cs0 + v1a * sn0;
        const float r1b = v1b * cs1 - v2b * sn1, r2b = v2b * cs1 + v1b * sn1;
        const size_t out = (size_t)(bm + row) * DD + bn + col;
        if (z == 0) {
            *(uint32_t*)&g_Qh[out]      = pack_f16(r1a * QSC, r1b * QSC);
            *(uint32_t*)&g_Qh[out + 32] = pack_f16(r2a * QSC, r2b * QSC);
        } else {
            *(uint32_t*)&g_Kh[out]      = pack_f16(r1a, r1b);
            *(uint32_t*)&g_Kh[out + 32] = pack_f16(r2a, r2b);
        }
    }
}

// ---------------------------------------------------------------------------
// O-projection GEMM: out = A @ Wo^T + bo, fp32 out.
// ---------------------------------------------------------------------------
__global__ __launch_bounds__(256, 2) void gemm_o_kernel(
    const float* __restrict__ bias, float* __restrict__ C)
{
    extern __shared__ char sm[];
    const uint32_t smb = smem_u32(sm);
    const int tid = threadIdx.x;
    const int wid = tid >> 5, lid = tid & 31;
    const int bm = blockIdx.y * 128, bn = blockIdx.x * 128;
    const int warp_m = wid & 1, warp_n = wid >> 1;

    const __nv_bfloat16* srcs[4] = {
        g_Ahi + (size_t)bm * DD, g_Alo + (size_t)bm * DD,
        g_Woh + (size_t)bn * DD, g_Wol + (size_t)bn * DD };

    float acc[4][4][4];
#pragma unroll
    for (int i = 0; i < 4; i++)
#pragma unroll
        for (int j = 0; j < 4; j++)
#pragma unroll
            for (int v = 0; v < 4; v++) acc[i][j][v] = 0.f;

    gemm_core(srcs, smb, tid, wid, lid, acc);

    const int gr = lid >> 2, gc = lid & 3;
#pragma unroll
    for (int nt = 0; nt < 4; nt++) {
        const int col = bn + warp_n * 32 + nt * 8 + gc * 2;
        const float2 bv = *(const float2*)(bias + col);
#pragma unroll
        for (int mt = 0; mt < 4; mt++) {
            const int row = bm + warp_m * 64 + mt * 16 + gr;
            *(float2*)(C + (size_t)row * DD + col) =
                make_float2(acc[mt][nt][0] + bv.x, acc[mt][nt][1] + bv.y);
            *(float2*)(C + (size_t)(row + 8) * DD + col) =
                make_float2(acc[mt][nt][2] + bv.x, acc[mt][nt][3] + bv.y);
        }
    }
}

// ---------------------------------------------------------------------------
// HMMA causal flash attention, all-single-fp16 operands. 2 CTAs/SM.
// NEW layout: 128 threads, 4 warps x 32 q-rows (two m-halves per warp).
// Each bK/bV ldsm now feeds 2x the MMAs (ratio 2 -> 4); ldsm count halved;
// barrier participants halved. Per-row math identical -> bit-exact vs R15.
// BR=128, BC=64, two K-tiles per barrier, 4 stage buffers.
// ---------------------------------------------------------------------------
#define AQ_B   18432            // 128*144
#define AARR_B 9216             // 64*144
#define ASTG_B (2 * AARR_B)     // 18432
#define ASMEM_TOTAL (AQ_B + 4 * ASTG_B)   // 92160

__global__ __launch_bounds__(128, 2) void attn_mma_kernel()
{
    extern __shared__ char sm[];
    const uint32_t smb = smem_u32(sm);
    const int tid = threadIdx.x;
    const int w = tid >> 5, lane = tid & 31;    // w in 0..3
    const int gr = lane >> 2, gc = lane & 3;
    const int qt = (int)gridDim.x - 1 - (int)blockIdx.x;   // long blocks first
    const int h = blockIdx.y, b = blockIdx.z;

    const size_t hb = ((size_t)b * SS) * DD + (size_t)h * HDIM;
    const size_t qrow0 = (size_t)qt * 128;

    const int ntiles = 2 * qt + 2;          // always even

    // --- prologue: Q tile (single fp16): 1024 chunks / 128 thr ---
#pragma unroll
    for (int i = 0; i < 8; i++) {
        int idx = tid + i * 128;
        int row = idx >> 3, c = idx & 7;
        cp16(smb + row * 144 + c * 16, g_Qh + hb + (qrow0 + row) * DD + c * 8);
    }
    CP_COMMIT();

    auto stage_load = [&](int jt, int s) {
        const uint32_t base = smb + AQ_B + (uint32_t)s * ASTG_B;
#pragma unroll
        for (int i = 0; i < 4; i++) {
            int idx = tid + i * 128;       // 512 chunks per array
            int row = idx >> 3, c = idx & 7;
            cp16(base + row * 144 + c * 16,
                 g_Kh + hb + (size_t)(jt * 64 + row) * DD + c * 8);
            cp16(base + AARR_B + row * 144 + c * 16,
                 g_Vh + hb + (size_t)(jt * 64 + row) * DD + c * 8);
        }
    };
    stage_load(0, 0); CP_COMMIT();
    stage_load(1, 1); CP_COMMIT();

    // Per m-half state. mh row base: qt*128 + w*32 + mh*16.
    float m0[2] = {-1e30f, -1e30f}, m1[2] = {-1e30f, -1e30f};
    float l0[2] = {0.f, 0.f}, l1[2] = {0.f, 0.f};
    float o[2][8][4];
#pragma unroll
    for (int mh = 0; mh < 2; mh++)
#pragma unroll
        for (int d = 0; d < 8; d++)
#pragma unroll
            for (int v = 0; v < 4; v++) o[mh][d][v] = 0.f;

    uint32_t aQ[2][4][4];
    const int qrow_lo0 = qt * 128 + w * 32 + gr;          // mh = 0
    const int qrow_lo1 = qrow_lo0 + 16;                   // mh = 1
    const int warp_row_max = qt * 128 + w * 32 + 31;

    // One warp-tile of attention for K-tile jt (buffers assumed resident).
    auto process_tile = [&](int jt) {
        if (jt * 64 > warp_row_max) return;   // fully causally masked

        const uint32_t stg = smb + AQ_B + (uint32_t)(jt & 3) * ASTG_B;

        // ---- S = Q K^T: shared bK feeds both m-halves ----
        float sc[2][8][4];
#pragma unroll
        for (int mh = 0; mh < 2; mh++)
#pragma unroll
            for (int nt = 0; nt < 8; nt++)
#pragma unroll
                for (int v = 0; v < 4; v++) sc[mh][nt][v] = 0.f;

        const uint32_t kaddr = stg
            + (uint32_t)((lane & 7) | ((lane & 16) >> 1)) * 144 + (lane & 8) * 2;
#pragma unroll
        for (int kt = 0; kt < 4; kt++) {
            uint32_t bK[4][4];
#pragma unroll
            for (int np = 0; np < 4; np++)
                ldsm4(bK[np], kaddr + np * 2304 + kt * 32);
#pragma unroll
            for (int np = 0; np < 4; np++)
#pragma unroll
                for (int mh = 0; mh < 2; mh++) {
                    mma_f16(sc[mh][2*np],   aQ[mh][kt], &bK[np][0]);
                    mma_f16(sc[mh][2*np+1], aQ[mh][kt], &bK[np][2]);
                }
        }

        // ---- causal mask (only last two tiles) ----
        if (jt >= 2 * qt) {
#pragma unroll
            for (int mh = 0; mh < 2; mh++) {
                const int qlo = (mh == 0) ? qrow_lo0 : qrow_lo1;
#pragma unroll
                for (int nt = 0; nt < 8; nt++) {
                    int j = jt * 64 + nt * 8 + gc * 2;
                    if (j     > qlo)     sc[mh][nt][0] = -1e30f;
                    if (j + 1 > qlo)     sc[mh][nt][1] = -1e30f;
                    if (j     > qlo + 8) sc[mh][nt][2] = -1e30f;
                    if (j + 1 > qlo + 8) sc[mh][nt][3] = -1e30f;
                }
            }
        }

        // ---- online softmax (exp2 domain) + packed P, per m-half ----
        uint32_t hP[2][8][2];
#pragma unroll
        for (int mh = 0; mh < 2; mh++) {
            float mx0 = -1e30f, mx1 = -1e30f;
#pragma unroll
            for (int nt = 0; nt < 8; nt++) {
                mx0 = fmaxf(mx0, fmaxf(sc[mh][nt][0], sc[mh][nt][1]));
                mx1 = fmaxf(mx1, fmaxf(sc[mh][nt][2], sc[mh][nt][3]));
            }
            mx0 = fmaxf(mx0, __shfl_xor_sync(0xffffffffu, mx0, 1));
            mx0 = fmaxf(mx0, __shfl_xor_sync(0xffffffffu, mx0, 2));
            mx1 = fmaxf(mx1, __shfl_xor_sync(0xffffffffu, mx1, 1));
            mx1 = fmaxf(mx1, __shfl_xor_sync(0xffffffffu, mx1, 2));

            float mn0 = fmaxf(m0[mh], mx0), mn1 = fmaxf(m1[mh], mx1);
            float al0 = exp2f(m0[mh] - mn0), al1 = exp2f(m1[mh] - mn1);
            m0[mh] = mn0; m1[mh] = mn1;

#pragma unroll
            for (int nt = 0; nt < 8; nt++) {
                hP[mh][nt][0] = ex2_f16x2(
                    pack_f16(sc[mh][nt][0] - mn0, sc[mh][nt][1] - mn0));
                hP[mh][nt][1] = ex2_f16x2(
                    pack_f16(sc[mh][nt][2] - mn1, sc[mh][nt][3] - mn1));
            }

            // row sums via ones-MMA: exact fp32, no shuffles
            float lacc[4] = {0.f, 0.f, 0.f, 0.f};
            const uint32_t bOnes[2] = {0x3C003C00u, 0x3C003C00u};
#pragma unroll
            for (int kt = 0; kt < 4; kt++) {
                uint32_t aP[4] = {hP[mh][2*kt][0], hP[mh][2*kt][1],
                                  hP[mh][2*kt+1][0], hP[mh][2*kt+1][1]};
                mma_f16(lacc, aP, bOnes);
            }
            l0[mh] = l0[mh] * al0 + lacc[0];
            l1[mh] = l1[mh] * al1 + lacc[2];
#pragma unroll
            for (int d = 0; d < 8; d++) {
                o[mh][d][0] *= al0; o[mh][d][1] *= al0;
                o[mh][d][2] *= al1; o[mh][d][3] *= al1;
            }
        }

        // ---- O += P V: shared bV feeds both m-halves ----
        const uint32_t vaddr = stg + AARR_B
            + (uint32_t)(lane & 15) * 144 + (lane >> 4) * 16;
#pragma unroll
        for (int kt = 0; kt < 4; kt++) {
            uint32_t bV[4][4];
#pragma unroll
            for (int dp = 0; dp < 4; dp++)
                ldsm4t(bV[dp], vaddr + kt * 2304 + dp * 32);
#pragma unroll
            for (int mh = 0; mh < 2; mh++) {
                uint32_t aP[4] = {hP[mh][2*kt][0], hP[mh][2*kt][1],
                                  hP[mh][2*kt+1][0], hP[mh][2*kt+1][1]};
#pragma unroll
                for (int dp = 0; dp < 4; dp++) {
                    mma_f16(o[mh][2*dp],   aP, &bV[dp][0]);
                    mma_f16(o[mh][2*dp+1], aP, &bV[dp][2]);
                }
            }
        }
    };

    // Main loop: two K-tiles per pipeline step (one wait + one barrier/pair).
    const int npairs = ntiles >> 1;
    for (int ip = 0; ip < npairs; ip++) {
        const int t0 = 2 * ip;
        CP_WAIT(0);
        __syncthreads();

        if (ip == 0) {   // Q fragments (loop-invariant; Q group completed)
#pragma unroll
            for (int mh = 0; mh < 2; mh++) {
                const uint32_t qa = smb
                    + (uint32_t)(w * 32 + mh * 16 + (lane & 15)) * 144
                    + (lane >> 4) * 16;
#pragma unroll
                for (int kt = 0; kt < 4; kt++) ldsm4(aQ[mh][kt], qa + kt * 32);
            }
        }

        if (t0 + 2 < ntiles) { stage_load(t0 + 2, (t0 + 2) & 3); CP_COMMIT(); }
        if (t0 + 3 < ntiles) { stage_load(t0 + 3, (t0 + 3) & 3); CP_COMMIT(); }

        process_tile(t0);
        process_tile(t0 + 1);
    }

    // ---- epilogue: /l, split to bf16 hi/lo for O-projection ----
#pragma unroll
    for (int mh = 0; mh < 2; mh++) {
        const float inv0 = 1.0f / l0[mh], inv1 = 1.0f / l1[mh];
        const size_t rbase = qrow0 + w * 32 + mh * 16 + gr;
#pragma unroll
        for (int dt = 0; dt < 8; dt++) {
            size_t idx = hb + rbase * DD + dt * 8 + gc * 2;
            uint32_t hh, ll;
            cvt_split2(o[mh][dt][0] * inv0, o[mh][dt][1] * inv0, hh, ll);
            *(uint32_t*)&g_Ahi[idx] = hh;
            *(uint32_t*)&g_Alo[idx] = ll;
            size_t idx8 = idx + 8 * DD;
            cvt_split2(o[mh][dt][2] * inv1, o[mh][dt][3] * inv1, hh, ll);
            *(uint32_t*)&g_Ahi[idx8] = hh;
            *(uint32_t*)&g_Alo[idx8] = ll;
        }
    }
}

// ---------------------------------------------------------------------------
extern "C" void kernel_launch(void* const* d_in, const int* in_sizes, int n_in,
                              void* d_out, int out_size)
{
    (void)in_sizes; (void)n_in; (void)out_size;
    const float* x  = (const float*)d_in[0];
    const float* Wq = (const float*)d_in[1];
    const float* bq = (const float*)d_in[2];
    const float* Wk = (const float*)d_in[3];
    const float* bk = (const float*)d_in[4];
    const float* Wv = (const float*)d_in[5];
    const float* bv = (const float*)d_in[6];
    const float* Wo = (const float*)d_in[7];
    const float* bo = (const float*)d_in[8];
    float* out = (float*)d_out;

    __nv_bfloat16 *xh, *xl;
    cudaGetSymbolAddress((void**)&xh, g_xhi);
    cudaGetSymbolAddress((void**)&xl, g_xlo);

    cudaFuncSetAttribute(gemm_qkv_kernel,
                         cudaFuncAttributeMaxDynamicSharedMemorySize, GSMEM_TOTAL);
    cudaFuncSetAttribute(gemm_o_kernel,
                         cudaFuncAttributeMaxDynamicSharedMemorySize, GSMEM_TOTAL);
    cudaFuncSetAttribute(attn_mma_kernel,
                         cudaFuncAttributeMaxDynamicSharedMemorySize, ASMEM_TOTAL);

    prep_kernel<<<12544, 256>>>(x, Wq, Wk, Wv, Wo);

    gemm_qkv_kernel<<<dim3(DD / 128, MM / 128, 3), 256, GSMEM_TOTAL>>>(
        xh, xl, bq, bk, bv);

    attn_mma_kernel<<<dim3(SS / 128, HH, BB), 128, ASMEM_TOTAL>>>();

    gemm_o_kernel<<<dim3(DD / 128, MM / 128), 256, GSMEM_TOTAL>>>(bo, out);
}